// round 10
// baseline (speedup 1.0000x reference)
#include <cuda_runtime.h>
#include <cuda_bf16.h>
#include <cstdint>
#include <cstddef>

// ---------------------------------------------------------------------------
// mulGCN: two-branch GCN forward, split-bf16 mma.sync GEMMs with pre-split
// operands + cp.async double-buffered pipeline + ldmatrix fragment loads.
// R10: fragment loads via ldmatrix.m8n8.x4 (A: 8 ops, B: 16 ops per warp-chunk
// vs 96 scalar LDS); weights staged n-major [n][kp] to suit B ldmatrix.
// Two-branch stream pipeline identical to R9.
// Split-bf16: x = hi(trunc bf16, exact) + lo(bf16 rn of remainder);
// A@B ~= AhiBhi + AhiBlo + AloBhi, fp32 accum -> ~2e-5 rel error.
// ---------------------------------------------------------------------------

#define N_NODES   50000
#define N_EDGES   800000
#define DFEAT     256
#define G_FEAT    200
#define N_GRAPHS  512

#define NW   (N_NODES * 128)          // words per branch for split arrays

#define SCAN_BLKS   49                // ceil(50000/1024)
#define SCAN_CHUNK  1024

__device__ float    g_hW  [2][(size_t)N_NODES * DFEAT];   // reused as h2
__device__ float    g_agg [2][(size_t)N_NODES * DFEAT];
__device__ uint32_t g_nfH [2][(size_t)NW];
__device__ uint32_t g_nfL [2][(size_t)NW];
__device__ uint32_t g_h1H [2][(size_t)NW];
__device__ uint32_t g_h1L [2][(size_t)NW];
__device__ uint32_t g_WH  [6][256 * 128];   // n-major: [n][kp]
__device__ uint32_t g_WL  [6][256 * 128];
__device__ float    g_T   [2][N_GRAPHS * DFEAT];
__device__ int      g_counts  [2][N_GRAPHS];
__device__ int      g_deg     [2][N_NODES];
__device__ int      g_rowstart[2][N_NODES + 1];
__device__ int      g_cursor  [2][N_NODES];
__device__ int      g_csr_src [2][N_EDGES];
__device__ int      g_bsums   [2 * SCAN_BLKS];

__device__ __forceinline__ float frelu(float x) { return x > 0.f ? x : 0.f; }

// ------------------------- mma / pack / ldmatrix helpers -------------------
__device__ __forceinline__ void mma16816(float* c, const uint32_t* a,
                                         uint32_t b0, uint32_t b1) {
    asm volatile(
        "mma.sync.aligned.m16n8k16.row.col.f32.bf16.bf16.f32 "
        "{%0,%1,%2,%3}, {%4,%5,%6,%7}, {%8,%9}, {%0,%1,%2,%3};\n"
        : "+f"(c[0]), "+f"(c[1]), "+f"(c[2]), "+f"(c[3])
        : "r"(a[0]), "r"(a[1]), "r"(a[2]), "r"(a[3]), "r"(b0), "r"(b1));
}

#define LDSM4(r0, r1, r2, r3, addr) \
    asm volatile("ldmatrix.sync.aligned.m8n8.x4.shared.b16 {%0,%1,%2,%3}, [%4];" \
        : "=r"(r0), "=r"(r1), "=r"(r2), "=r"(r3) : "r"(addr))

__device__ __forceinline__ uint32_t pack_hi(float x, float y) {
    return __byte_perm(__float_as_uint(x), __float_as_uint(y), 0x7632);
}
__device__ __forceinline__ uint32_t pack_lo(float x, float y) {
    float hx = __uint_as_float(__float_as_uint(x) & 0xFFFF0000u);
    float hy = __uint_as_float(__float_as_uint(y) & 0xFFFF0000u);
    __nv_bfloat162 t;
    t.x = __float2bfloat16(x - hx);
    t.y = __float2bfloat16(y - hy);
    return *reinterpret_cast<uint32_t*>(&t);
}

// ------------------------- cp.async helpers --------------------------------
__device__ __forceinline__ void cp16(uint32_t dst, const void* src) {
    asm volatile("cp.async.cg.shared.global [%0], [%1], 16;"
                 :: "r"(dst), "l"(src));
}
__device__ __forceinline__ void cp16z(uint32_t dst, const void* src, bool ok) {
    int b = ok ? 16 : 0;
    asm volatile("cp.async.cg.shared.global [%0], [%1], 16, %2;"
                 :: "r"(dst), "l"(src), "r"(b));
}
#define CP_COMMIT()  asm volatile("cp.async.commit_group;" ::: "memory")
#define CP_WAIT1()   asm volatile("cp.async.wait_group 1;" ::: "memory")
#define CP_WAIT0()   asm volatile("cp.async.wait_group 0;" ::: "memory")

// SMEM words per buffer:
//   AH[128 rows][20]  AL[128][20]   (rows x k-pair words, pad 20)
//   BH[128 n][20]     BL[128][20]   (n rows x k-pair words, pad 20)
static constexpr int W_AH = 0, W_AL = 2560, W_BH = 5120, W_BL = 7680;
static constexpr int WBUF = 10240;
static constexpr int SMEM_BYTES = 2 * WBUF * 4;        // 81920

__device__ __forceinline__ void cpA(uint32_t sb, const uint32_t* __restrict__ AH,
                                    const uint32_t* __restrict__ AL,
                                    int M, int rowBase, int c, int tid)
{
    #pragma unroll
    for (int t = 0; t < 4; t++) {
        int idx = tid + t * 256;          // 0..1023
        int r   = idx >> 3;
        int seg = idx & 7;                // 0..7 (0-3 hi, 4-7 lo)
        int row = rowBase + r;
        bool ok = row < M;
        int rowc = ok ? row : 0;
        int s4 = (seg & 3) * 4;
        const uint32_t* src = (seg < 4 ? AH : AL) + (size_t)rowc * 128 + c * 16 + s4;
        uint32_t dst = sb + ((seg < 4 ? W_AH : W_AL) + r * 20 + s4) * 4;
        cp16z(dst, src, ok);
    }
}

// B fill from n-major weights [n][kp]: chunk c -> words kp in [c*16, c*16+16)
__device__ __forceinline__ void cpB(uint32_t sb, const uint32_t* __restrict__ WH,
                                    const uint32_t* __restrict__ WL,
                                    int colBase, int c, int tid)
{
    #pragma unroll
    for (int t = 0; t < 4; t++) {
        int idx  = tid + t * 256;         // 0..1023
        int nloc = idx >> 3;              // 0..127
        int seg  = idx & 7;
        int arr  = seg >> 2;              // 0 hi, 1 lo
        int s4   = (seg & 3) * 4;
        const uint32_t* src = (arr ? WL : WH)
            + (size_t)(colBase + nloc) * 128 + c * 16 + s4;
        uint32_t dst = sb + ((arr ? W_BL : W_BH) + nloc * 20 + s4) * 4;
        cp16(dst, src);
    }
}

// ---------------------------------------------------------------------------
// mma GEMM (single branch): 256 threads, 8 warps (4m x 2n), warp tile 32x64.
// Grid (ceil(M/128), 2).
// MODE 0: C fp32 = acc
// MODE 1: CH/CL split = pack(relu(acc+bias)+relu(agg+bagg))
// MODE 2: C fp32 = relu(acc+bias)
// ---------------------------------------------------------------------------
template<int MODE>
__global__ __launch_bounds__(256, 2)
void gemm_mma(const uint32_t* __restrict__ AH, const uint32_t* __restrict__ AL,
              const uint32_t* __restrict__ WH, const uint32_t* __restrict__ WL,
              const float* __restrict__ bias,
              const float* __restrict__ agg,
              const float* __restrict__ bagg,
              float* __restrict__ C,
              uint32_t* __restrict__ CH, uint32_t* __restrict__ CL,
              int M)
{
    extern __shared__ uint32_t sm[];
    const int tid  = threadIdx.x;
    const int lane = tid & 31;
    const int wid  = tid >> 5;
    const int wm   = wid & 3;
    const int wn   = wid >> 2;
    const int gid  = lane >> 2;
    const int tig  = lane & 3;
    const int rowBase = blockIdx.x * 128;
    const int colBase = blockIdx.y * 128;

    uint32_t sbase;
    {
        uint64_t a = __cvta_generic_to_shared(sm);
        sbase = (uint32_t)a;
    }

    // Per-thread ldmatrix lane offsets (in words).
    // A x4 mats: (m0-7,k0-7)(m8-15,k0-7)(m0-7,k8-15)(m8-15,k8-15)
    const int mloc   = (lane & 7) + ((lane >> 3) & 1) * 8;
    const int khalfA = (lane >> 4) & 1;
    const int aoffw  = (wm * 32 + mloc) * 20 + khalfA * 4;
    // B x4 mats per nt-pair: (nt_e,k0-7)(nt_e,k8-15)(nt_o,k0-7)(nt_o,k8-15)
    const int nloc   = (lane & 7) + ((lane >> 4) & 1) * 8;
    const int khalfB = (lane >> 3) & 1;
    const int boffw  = (wn * 64 + nloc) * 20 + khalfB * 4;

    float acc[2][8][4];
    #pragma unroll
    for (int mt = 0; mt < 2; mt++)
        #pragma unroll
        for (int nt = 0; nt < 8; nt++)
            #pragma unroll
            for (int q = 0; q < 4; q++) acc[mt][nt][q] = 0.f;

    cpA(sbase, AH, AL, M, rowBase, 0, tid);
    cpB(sbase, WH, WL, colBase, 0, tid);
    CP_COMMIT();

    #pragma unroll
    for (int c = 0; c < 8; c++) {
        if (c < 7) {
            uint32_t nb = sbase + ((c + 1) & 1) * (WBUF * 4);
            cpA(nb, AH, AL, M, rowBase, c + 1, tid);
            cpB(nb, WH, WL, colBase, c + 1, tid);
            CP_COMMIT();
            CP_WAIT1();
        } else {
            CP_WAIT0();
        }
        __syncthreads();

        const uint32_t bufb = sbase + (c & 1) * (WBUF * 4);

        #pragma unroll
        for (int ks = 0; ks < 2; ks++) {
            uint32_t aH[2][4], aL[2][4];
            #pragma unroll
            for (int mt = 0; mt < 2; mt++) {
                uint32_t aa = bufb + (W_AH + aoffw + mt * 320 + ks * 8) * 4;
                LDSM4(aH[mt][0], aH[mt][1], aH[mt][2], aH[mt][3], aa);
                uint32_t al = bufb + (W_AL + aoffw + mt * 320 + ks * 8) * 4;
                LDSM4(aL[mt][0], aL[mt][1], aL[mt][2], aL[mt][3], al);
            }
            #pragma unroll
            for (int ntp = 0; ntp < 4; ntp++) {
                uint32_t bh0e, bh1e, bh0o, bh1o;
                uint32_t bl0e, bl1e, bl0o, bl1o;
                uint32_t bh = bufb + (W_BH + boffw + ntp * 320 + ks * 8) * 4;
                LDSM4(bh0e, bh1e, bh0o, bh1o, bh);
                uint32_t bl = bufb + (W_BL + boffw + ntp * 320 + ks * 8) * 4;
                LDSM4(bl0e, bl1e, bl0o, bl1o, bl);
                int nte = 2 * ntp, nto = nte + 1;
                #pragma unroll
                for (int mt = 0; mt < 2; mt++) {
                    mma16816(acc[mt][nte], aH[mt], bh0e, bh1e);
                    mma16816(acc[mt][nte], aH[mt], bl0e, bl1e);
                    mma16816(acc[mt][nte], aL[mt], bh0e, bh1e);
                    mma16816(acc[mt][nto], aH[mt], bh0o, bh1o);
                    mma16816(acc[mt][nto], aH[mt], bl0o, bl1o);
                    mma16816(acc[mt][nto], aL[mt], bh0o, bh1o);
                }
            }
        }
        __syncthreads();
    }

    // ------------------------------ epilogue -------------------------------
    #pragma unroll
    for (int mt = 0; mt < 2; mt++) {
        #pragma unroll
        for (int nt = 0; nt < 8; nt++) {
            int r0  = rowBase + wm * 32 + mt * 16 + gid;
            int r1  = r0 + 8;
            int col = colBase + wn * 64 + nt * 8 + 2 * tig;
            float* a4 = acc[mt][nt];
            if (MODE == 0) {
                if (r0 < M)
                    *reinterpret_cast<float2*>(C + (size_t)r0 * 256 + col) =
                        make_float2(a4[0], a4[1]);
                if (r1 < M)
                    *reinterpret_cast<float2*>(C + (size_t)r1 * 256 + col) =
                        make_float2(a4[2], a4[3]);
            } else if (MODE == 1) {
                float2 bs = *reinterpret_cast<const float2*>(bias + col);
                float2 ba = *reinterpret_cast<const float2*>(bagg + col);
                if (r0 < M) {
                    float2 ag = *reinterpret_cast<const float2*>(agg + (size_t)r0 * 256 + col);
                    float v0 = frelu(a4[0] + bs.x) + frelu(ag.x + ba.x);
                    float v1 = frelu(a4[1] + bs.y) + frelu(ag.y + ba.y);
                    CH[(size_t)r0 * 128 + (col >> 1)] = pack_hi(v0, v1);
                    CL[(size_t)r0 * 128 + (col >> 1)] = pack_lo(v0, v1);
                }
                if (r1 < M) {
                    float2 ag = *reinterpret_cast<const float2*>(agg + (size_t)r1 * 256 + col);
                    float v0 = frelu(a4[2] + bs.x) + frelu(ag.x + ba.x);
                    float v1 = frelu(a4[3] + bs.y) + frelu(ag.y + ba.y);
                    CH[(size_t)r1 * 128 + (col >> 1)] = pack_hi(v0, v1);
                    CL[(size_t)r1 * 128 + (col >> 1)] = pack_lo(v0, v1);
                }
            } else {
                float2 bs = *reinterpret_cast<const float2*>(bias + col);
                if (r0 < M)
                    *reinterpret_cast<float2*>(C + (size_t)r0 * 256 + col) =
                        make_float2(frelu(a4[0] + bs.x), frelu(a4[1] + bs.y));
                if (r1 < M)
                    *reinterpret_cast<float2*>(C + (size_t)r1 * 256 + col) =
                        make_float2(frelu(a4[2] + bs.x), frelu(a4[3] + bs.y));
            }
        }
    }
}

// ---------------------------------------------------------------------------
// Conversion kernels
// ---------------------------------------------------------------------------
__global__ __launch_bounds__(256)
void conv_nf(const float* __restrict__ n1, const float* __restrict__ n2,
             uint32_t* __restrict__ H, uint32_t* __restrict__ L)
{
    size_t idx = (size_t)blockIdx.x * blockDim.x + threadIdx.x;
    if (idx >= 2 * (size_t)NW) return;
    int br = idx >= (size_t)NW;
    size_t w = idx - (size_t)br * NW;
    const float* nf = br ? n2 : n1;
    float2 v = *reinterpret_cast<const float2*>(nf + w * 2);
    H[idx] = pack_hi(v.x, v.y);
    L[idx] = pack_lo(v.x, v.y);
}

// Weights to n-major split layout: WH[m][n*128 + kp] = pack(W[2kp][n], W[2kp+1][n])
__global__ __launch_bounds__(256)
void conv_W(const float* __restrict__ m0, const float* __restrict__ m1,
            const float* __restrict__ m2, const float* __restrict__ m3,
            const float* __restrict__ m4, const float* __restrict__ m5,
            uint32_t* __restrict__ WH, uint32_t* __restrict__ WL)
{
    int idx = blockIdx.x * blockDim.x + threadIdx.x;
    if (idx >= 6 * 256 * 128) return;
    int m    = idx >> 15;
    int rest = idx & 32767;
    int n    = rest >> 7;      // 0..255
    int kp   = rest & 127;     // 0..127
    const float* Wm = (m == 0) ? m0 : (m == 1) ? m1 : (m == 2) ? m2
                    : (m == 3) ? m3 : (m == 4) ? m4 : m5;
    float a = Wm[(size_t)(2 * kp) * 256 + n];
    float b = Wm[(size_t)(2 * kp + 1) * 256 + n];
    WH[idx] = pack_hi(a, b);
    WL[idx] = pack_lo(a, b);
}

// ---------------------------------------------------------------------------
// CSR build, both branches (runs on s2, overlapped)
// ---------------------------------------------------------------------------
__global__ void hist_kernel(const int* __restrict__ dst1, const int* __restrict__ dst2,
                            int* __restrict__ deg)
{
    int idx = blockIdx.x * blockDim.x + threadIdx.x;
    if (idx < 2 * N_EDGES) {
        int br = idx >= N_EDGES;
        int e  = idx - br * N_EDGES;
        int d  = br ? dst2[e] : dst1[e];
        atomicAdd(&deg[br * N_NODES + d], 1);
    }
}

__global__ __launch_bounds__(256)
void scan1_kernel(const int* __restrict__ degAll, int* __restrict__ rowstartAll,
                  int* __restrict__ bsums)
{
    __shared__ int wsum[8];
    int br  = blockIdx.x / SCAN_BLKS;
    int blk = blockIdx.x % SCAN_BLKS;
    int t = threadIdx.x, lane = t & 31, w = t >> 5;
    const int* deg = degAll + br * N_NODES;
    int* rowstart  = rowstartAll + br * (N_NODES + 1);

    int base = blk * SCAN_CHUNK + t * 4;
    int v[4];
    #pragma unroll
    for (int i = 0; i < 4; i++)
        v[i] = (base + i < N_NODES) ? deg[base + i] : 0;
    int s = v[0] + v[1] + v[2] + v[3];

    int x = s;
    #pragma unroll
    for (int o = 1; o < 32; o <<= 1) {
        int n = __shfl_up_sync(0xFFFFFFFFu, x, o);
        if (lane >= o) x += n;
    }
    if (lane == 31) wsum[w] = x;
    __syncthreads();
    if (w == 0 && lane < 8) {
        int y = wsum[lane];
        #pragma unroll
        for (int o = 1; o < 8; o <<= 1) {
            int n = __shfl_up_sync(0xFFu, y, o);
            if (lane >= o) y += n;
        }
        wsum[lane] = y;
    }
    __syncthreads();
    int excl = x - s + (w > 0 ? wsum[w - 1] : 0);

    int run = excl;
    #pragma unroll
    for (int i = 0; i < 4; i++) {
        if (base + i < N_NODES) rowstart[base + i] = run;
        run += v[i];
    }
    if (t == 255) bsums[br * SCAN_BLKS + blk] = wsum[7];
}

__global__ __launch_bounds__(256)
void scan2_kernel(const int* __restrict__ bsums, int* __restrict__ rowstartAll,
                  int* __restrict__ cursorAll)
{
    __shared__ int soff;
    int br  = blockIdx.x / SCAN_BLKS;
    int blk = blockIdx.x % SCAN_BLKS;
    int t = threadIdx.x;
    int* rowstart = rowstartAll + br * (N_NODES + 1);
    int* cursor   = cursorAll   + br * N_NODES;

    if (t == 0) {
        int off = 0;
        for (int j = 0; j < blk; j++) off += bsums[br * SCAN_BLKS + j];
        soff = off;
        if (blockIdx.x == 0) {
            rowstartAll[N_NODES] = N_EDGES;
            rowstartAll[(N_NODES + 1) + N_NODES] = N_EDGES;
        }
    }
    __syncthreads();
    int off = soff;
    int base = blk * SCAN_CHUNK + t * 4;
    #pragma unroll
    for (int i = 0; i < 4; i++) {
        int g = base + i;
        if (g < N_NODES) {
            int val = rowstart[g] + off;
            rowstart[g] = val;
            cursor[g]   = val;
        }
    }
}

__global__ void fill_kernel(const int* __restrict__ src1, const int* __restrict__ dst1,
                            const int* __restrict__ src2, const int* __restrict__ dst2,
                            int* __restrict__ cursorAll, int* __restrict__ csrAll)
{
    int idx = blockIdx.x * blockDim.x + threadIdx.x;
    if (idx < 2 * N_EDGES) {
        int br = idx >= N_EDGES;
        int e  = idx - br * N_EDGES;
        int d  = br ? dst2[e] : dst1[e];
        int s  = br ? src2[e] : src1[e];
        int p  = atomicAdd(&cursorAll[br * N_NODES + d], 1);
        csrAll[br * N_EDGES + p] = s;
    }
}

// ---------------------------------------------------------------------------
// Warp-per-node gather (single branch)
// ---------------------------------------------------------------------------
__global__ __launch_bounds__(256)
void gather_kernel(const float* __restrict__ hW,
                   const int* __restrict__ rowstart,
                   const int* __restrict__ csr,
                   float* __restrict__ agg)
{
    int node = (blockIdx.x * blockDim.x + threadIdx.x) >> 5;
    int lane = threadIdx.x & 31;
    if (node >= N_NODES) return;

    int beg = rowstart[node], end = rowstart[node + 1];
    float4 a0 = make_float4(0.f, 0.f, 0.f, 0.f);
    float4 a1 = make_float4(0.f, 0.f, 0.f, 0.f);
    float4 b0 = make_float4(0.f, 0.f, 0.f, 0.f);
    float4 b1 = make_float4(0.f, 0.f, 0.f, 0.f);
    int e = beg;
    for (; e + 1 < end; e += 2) {
        const float4* r0 = reinterpret_cast<const float4*>(hW + (size_t)csr[e]     * DFEAT);
        const float4* r1 = reinterpret_cast<const float4*>(hW + (size_t)csr[e + 1] * DFEAT);
        float4 u0 = r0[lane], u1 = r0[lane + 32];
        float4 v0 = r1[lane], v1 = r1[lane + 32];
        a0.x += u0.x; a0.y += u0.y; a0.z += u0.z; a0.w += u0.w;
        a1.x += u1.x; a1.y += u1.y; a1.z += u1.z; a1.w += u1.w;
        b0.x += v0.x; b0.y += v0.y; b0.z += v0.z; b0.w += v0.w;
        b1.x += v1.x; b1.y += v1.y; b1.z += v1.z; b1.w += v1.w;
    }
    if (e < end) {
        const float4* r0 = reinterpret_cast<const float4*>(hW + (size_t)csr[e] * DFEAT);
        float4 u0 = r0[lane], u1 = r0[lane + 32];
        a0.x += u0.x; a0.y += u0.y; a0.z += u0.z; a0.w += u0.w;
        a1.x += u1.x; a1.y += u1.y; a1.z += u1.z; a1.w += u1.w;
    }
    a0.x += b0.x; a0.y += b0.y; a0.z += b0.z; a0.w += b0.w;
    a1.x += b1.x; a1.y += b1.y; a1.z += b1.z; a1.w += b1.w;
    float4* out = reinterpret_cast<float4*>(agg + (size_t)node * DFEAT);
    out[lane]      = a0;
    out[lane + 32] = a1;
}

// ---------------------------------------------------------------------------
// Segment sum (sorted gid), single branch
// ---------------------------------------------------------------------------
__global__ __launch_bounds__(256)
void segsum_kernel(const float* __restrict__ h2, const int* __restrict__ gid,
                   float* __restrict__ T, int* __restrict__ counts)
{
    __shared__ int sb, se;
    int g = blockIdx.x;
    if (threadIdx.x == 0) {
        int lo = 0, hi = N_NODES;
        while (lo < hi) { int m = (lo + hi) >> 1; if (gid[m] < g) lo = m + 1; else hi = m; }
        sb = lo;
        lo = sb; hi = N_NODES;
        while (lo < hi) { int m = (lo + hi) >> 1; if (gid[m] < g + 1) lo = m + 1; else hi = m; }
        se = lo;
        counts[g] = se - sb;
    }
    __syncthreads();
    int beg = sb, end = se, c = threadIdx.x;
    float s = 0.f;
    for (int r = beg; r < end; r++)
        s += h2[(size_t)r * DFEAT + c];
    T[(size_t)g * DFEAT + c] = s;
}

// ---------------------------------------------------------------------------
// Fused readout + predictor
// ---------------------------------------------------------------------------
__global__ __launch_bounds__(256)
void readout_final(const float* __restrict__ TAll, const int* __restrict__ countsAll,
                   const float* __restrict__ Ro1, const float* __restrict__ rbo1,
                   const float* __restrict__ Ro2, const float* __restrict__ rbo2,
                   const float* __restrict__ Wp, const float* __restrict__ bp,
                   float* __restrict__ out)
{
    __shared__ float ts1[DFEAT], ts2[DFEAT];
    __shared__ float red[256];
    int g = blockIdx.x;
    int t = threadIdx.x;
    ts1[t] = TAll[(size_t)g * DFEAT + t];
    ts2[t] = TAll[((size_t)N_GRAPHS + g) * DFEAT + t];
    __syncthreads();
    float c1 = (float)countsAll[g];
    float c2 = (float)countsAll[N_GRAPHS + g];
    float partial = 0.f;
    if (t < G_FEAT) {
        float s = c1 * rbo1[t] + c2 * rbo2[t];
        #pragma unroll 8
        for (int k = 0; k < DFEAT; k++)
            s += ts1[k] * Ro1[(size_t)k * G_FEAT + t]
               + ts2[k] * Ro2[(size_t)k * G_FEAT + t];
        partial = s * Wp[t];
    }
    red[t] = partial;
    __syncthreads();
    #pragma unroll
    for (int st = 128; st > 0; st >>= 1) {
        if (t < st) red[t] += red[t + st];
        __syncthreads();
    }
    if (t == 0) out[g] = red[0] + bp[0];
}

// ---------------------------------------------------------------------------
extern "C" void kernel_launch(void* const* d_in, const int* in_sizes, int n_in,
                              void* d_out, int out_size)
{
    const float* nf1 = (const float*)d_in[0];
    const float* nf2 = (const float*)d_in[2];
    const int* src1 = (const int*)d_in[4];
    const int* dst1 = (const int*)d_in[5];
    const int* gid1 = (const int*)d_in[6];
    const int* src2 = (const int*)d_in[7];
    const int* dst2 = (const int*)d_in[8];
    const int* gid2 = (const int*)d_in[9];
    const float* W1  = (const float*)d_in[10]; const float* b1  = (const float*)d_in[11];
    const float* Wr1 = (const float*)d_in[12]; const float* br1 = (const float*)d_in[13];
    const float* W2  = (const float*)d_in[14]; const float* b2  = (const float*)d_in[15];
    const float* Wr2 = (const float*)d_in[16]; const float* br2 = (const float*)d_in[17];
    const float* Ri1 = (const float*)d_in[18]; const float* rbi1 = (const float*)d_in[19];
    const float* Ro1 = (const float*)d_in[20]; const float* rbo1 = (const float*)d_in[21];
    const float* Ri2 = (const float*)d_in[22]; const float* rbi2 = (const float*)d_in[23];
    const float* Ro2 = (const float*)d_in[24]; const float* rbo2 = (const float*)d_in[25];
    const float* Wp  = (const float*)d_in[26]; const float* bp   = (const float*)d_in[27];

    float *hW, *agg, *T;
    uint32_t *nfH, *nfL, *h1H, *h1L, *WH, *WL;
    int *counts, *deg, *rowstart, *cursor, *csr_src, *bsums;
    cudaGetSymbolAddress((void**)&hW,       g_hW);
    cudaGetSymbolAddress((void**)&agg,      g_agg);
    cudaGetSymbolAddress((void**)&nfH,      g_nfH);
    cudaGetSymbolAddress((void**)&nfL,      g_nfL);
    cudaGetSymbolAddress((void**)&h1H,      g_h1H);
    cudaGetSymbolAddress((void**)&h1L,      g_h1L);
    cudaGetSymbolAddress((void**)&WH,       g_WH);
    cudaGetSymbolAddress((void**)&WL,       g_WL);
    cudaGetSymbolAddress((void**)&T,        g_T);
    cudaGetSymbolAddress((void**)&counts,   g_counts);
    cudaGetSymbolAddress((void**)&deg,      g_deg);
    cudaGetSymbolAddress((void**)&rowstart, g_rowstart);
    cudaGetSymbolAddress((void**)&cursor,   g_cursor);
    cudaGetSymbolAddress((void**)&csr_src,  g_csr_src);
    cudaGetSymbolAddress((void**)&bsums,    g_bsums);

    cudaFuncSetAttribute(gemm_mma<0>, cudaFuncAttributeMaxDynamicSharedMemorySize, SMEM_BYTES);
    cudaFuncSetAttribute(gemm_mma<1>, cudaFuncAttributeMaxDynamicSharedMemorySize, SMEM_BYTES);
    cudaFuncSetAttribute(gemm_mma<2>, cudaFuncAttributeMaxDynamicSharedMemorySize, SMEM_BYTES);

    // Lazy second stream + events (created on the first, uncaptured, call).
    static cudaStream_t s_s2 = nullptr;
    static cudaEvent_t  s_evF = nullptr, s_evCSR = nullptr, s_evConv = nullptr,
                        s_evJ = nullptr;
    static bool s_tried = false;
    if (!s_tried) {
        s_tried = true;
        if (cudaStreamCreateWithFlags(&s_s2, cudaStreamNonBlocking) != cudaSuccess)
            s_s2 = nullptr;
        if (s_s2) {
            if (cudaEventCreateWithFlags(&s_evF,   cudaEventDisableTiming) != cudaSuccess ||
                cudaEventCreateWithFlags(&s_evCSR, cudaEventDisableTiming) != cudaSuccess ||
                cudaEventCreateWithFlags(&s_evConv,cudaEventDisableTiming) != cudaSuccess ||
                cudaEventCreateWithFlags(&s_evJ,   cudaEventDisableTiming) != cudaSuccess) {
                s_s2 = nullptr;   // fall back to fully serial on stream 0
            }
        }
    }
    cudaStream_t s0 = (cudaStream_t)0;
    cudaStream_t s2 = s_s2 ? s_s2 : s0;

    float* hW1  = hW;   float* hW2  = hW  + (size_t)N_NODES * DFEAT;
    float* agg1 = agg;  float* agg2 = agg + (size_t)N_NODES * DFEAT;
    float* T1   = T;    float* T2   = T   + (size_t)N_GRAPHS * DFEAT;
    int* counts1 = counts;  int* counts2 = counts + N_GRAPHS;
    uint32_t* nfH1 = nfH; uint32_t* nfH2 = nfH + (size_t)NW;
    uint32_t* nfL1 = nfL; uint32_t* nfL2 = nfL + (size_t)NW;
    uint32_t* h1H1 = h1H; uint32_t* h1H2 = h1H + (size_t)NW;
    uint32_t* h1L1 = h1L; uint32_t* h1L2 = h1L + (size_t)NW;
    const int* rs1 = rowstart;              const int* rs2 = rowstart + (N_NODES + 1);
    const int* cs1 = csr_src;               const int* cs2 = csr_src + N_EDGES;
    uint32_t* WH_ = WH;  uint32_t* WL_ = WL;
    const int WSZ = 256 * 128;   // slots: 0=W1 1=Wr1 2=Ri1 3=W2 4=Wr2 5=Ri2

    dim3 gemm_grid((N_NODES + 127) / 128, 2);       // per-branch: 391 x 2
    int eb2 = (2 * N_EDGES + 255) / 256;
    int gat_blocks = (N_NODES * 32 + 255) / 256;

    // ---- fork ----
    if (s_s2) {
        cudaEventRecord(s_evF, s0);
        cudaStreamWaitEvent(s_s2, s_evF, 0);
    }

    // s2: CSR chain (both branches)
    cudaMemsetAsync(deg, 0, 2 * N_NODES * sizeof(int), s2);
    hist_kernel<<<eb2, 256, 0, s2>>>(dst1, dst2, deg);
    scan1_kernel<<<2 * SCAN_BLKS, 256, 0, s2>>>(deg, rowstart, bsums);
    scan2_kernel<<<2 * SCAN_BLKS, 256, 0, s2>>>(bsums, rowstart, cursor);
    fill_kernel<<<eb2, 256, 0, s2>>>(src1, dst1, src2, dst2, cursor, csr_src);
    if (s_s2) cudaEventRecord(s_evCSR, s_s2);

    // s0: conversions (both branches + all weights)
    conv_nf<<<(int)((2 * (size_t)NW + 255) / 256), 256, 0, s0>>>(nf1, nf2, nfH, nfL);
    conv_W<<<(6 * 256 * 128 + 255) / 256, 256, 0, s0>>>(W1, Wr1, Ri1, W2, Wr2, Ri2,
                                                        WH, WL);
    if (s_s2) cudaEventRecord(s_evConv, s0);

    // s0: branch-1 chain
    gemm_mma<0><<<gemm_grid, 256, SMEM_BYTES, s0>>>(
        nfH1, nfL1, WH_ + 0 * WSZ, WL_ + 0 * WSZ,
        nullptr, nullptr, nullptr, hW1, nullptr, nullptr, N_NODES);
    if (s_s2) cudaStreamWaitEvent(s0, s_evCSR, 0);
    gather_kernel<<<gat_blocks, 256, 0, s0>>>(hW1, rs1, cs1, agg1);
    gemm_mma<1><<<gemm_grid, 256, SMEM_BYTES, s0>>>(
        nfH1, nfL1, WH_ + 1 * WSZ, WL_ + 1 * WSZ,
        br1, agg1, b1, nullptr, h1H1, h1L1, N_NODES);
    gemm_mma<2><<<gemm_grid, 256, SMEM_BYTES, s0>>>(
        h1H1, h1L1, WH_ + 2 * WSZ, WL_ + 2 * WSZ,
        rbi1, nullptr, nullptr, hW1, nullptr, nullptr, N_NODES);
    segsum_kernel<<<N_GRAPHS, 256, 0, s0>>>(hW1, gid1, T1, counts1);

    // s2: branch-2 chain (needs conv for weights/features)
    if (s_s2) cudaStreamWaitEvent(s_s2, s_evConv, 0);
    gemm_mma<0><<<gemm_grid, 256, SMEM_BYTES, s2>>>(
        nfH2, nfL2, WH_ + 3 * WSZ, WL_ + 3 * WSZ,
        nullptr, nullptr, nullptr, hW2, nullptr, nullptr, N_NODES);
    gather_kernel<<<gat_blocks, 256, 0, s2>>>(hW2, rs2, cs2, agg2);
    gemm_mma<1><<<gemm_grid, 256, SMEM_BYTES, s2>>>(
        nfH2, nfL2, WH_ + 4 * WSZ, WL_ + 4 * WSZ,
        br2, agg2, b2, nullptr, h1H2, h1L2, N_NODES);
    gemm_mma<2><<<gemm_grid, 256, SMEM_BYTES, s2>>>(
        h1H2, h1L2, WH_ + 5 * WSZ, WL_ + 5 * WSZ,
        rbi2, nullptr, nullptr, hW2, nullptr, nullptr, N_NODES);
    segsum_kernel<<<N_GRAPHS, 256, 0, s2>>>(hW2, gid2, T2, counts2);
    if (s_s2) cudaEventRecord(s_evJ, s_s2);

    // join + fused readout/predictor
    if (s_s2) cudaStreamWaitEvent(s0, s_evJ, 0);
    readout_final<<<N_GRAPHS, 256, 0, s0>>>(T, counts, Ro1, rbo1, Ro2, rbo2, Wp, bp,
                                            (float*)d_out);
}

// round 11
// speedup vs baseline: 1.0137x; 1.0137x over previous
#include <cuda_runtime.h>
#include <cuda_bf16.h>
#include <cstdint>
#include <cstddef>

// ---------------------------------------------------------------------------
// mulGCN: two-branch GCN forward, split-bf16 mma.sync GEMMs with pre-split
// operands + cp.async double-buffered pipeline. Multi-block CSR scan.
// R11: gather commutes with projection — hagg = S.h on RAW features (depends
// only on CSR), then h1 = relu(hagg@W + b) + relu(h@Wr + br). Gather packs
// split-bf16 in its epilogue. 3-stream schedule: s2 CSR+gathers, s0 branch-1
// GEMMs, s3 branch-2 GEMMs. GEMM inner loop = R9 (ldmatrix reverted).
// Split-bf16: x = hi(trunc bf16, exact) + lo(bf16 rn of remainder);
// A@B ~= AhiBhi + AhiBlo + AloBhi, fp32 accum -> ~2e-5 rel error.
// ---------------------------------------------------------------------------

#define N_NODES   50000
#define N_EDGES   800000
#define DFEAT     256
#define G_FEAT    200
#define N_GRAPHS  512

#define NW   (N_NODES * 128)          // words per branch for split arrays

#define SCAN_BLKS   49                // ceil(50000/1024)
#define SCAN_CHUNK  1024

__device__ float    g_t2  [2][(size_t)N_NODES * DFEAT];   // h@Wr; reused as h2
__device__ uint32_t g_aggH[2][(size_t)NW];
__device__ uint32_t g_aggL[2][(size_t)NW];
__device__ uint32_t g_nfH [2][(size_t)NW];
__device__ uint32_t g_nfL [2][(size_t)NW];
__device__ uint32_t g_h1H [2][(size_t)NW];
__device__ uint32_t g_h1L [2][(size_t)NW];
__device__ uint32_t g_WH  [6][128 * 256];   // k-major pairs: [kp][n]
__device__ uint32_t g_WL  [6][128 * 256];
__device__ float    g_T   [2][N_GRAPHS * DFEAT];
__device__ int      g_counts  [2][N_GRAPHS];
__device__ int      g_deg     [2][N_NODES];
__device__ int      g_rowstart[2][N_NODES + 1];
__device__ int      g_cursor  [2][N_NODES];
__device__ int      g_csr_src [2][N_EDGES];
__device__ int      g_bsums   [2 * SCAN_BLKS];

__device__ __forceinline__ float frelu(float x) { return x > 0.f ? x : 0.f; }

// ------------------------- mma / pack helpers ------------------------------
__device__ __forceinline__ void mma16816(float* c, const uint32_t* a,
                                         uint32_t b0, uint32_t b1) {
    asm volatile(
        "mma.sync.aligned.m16n8k16.row.col.f32.bf16.bf16.f32 "
        "{%0,%1,%2,%3}, {%4,%5,%6,%7}, {%8,%9}, {%0,%1,%2,%3};\n"
        : "+f"(c[0]), "+f"(c[1]), "+f"(c[2]), "+f"(c[3])
        : "r"(a[0]), "r"(a[1]), "r"(a[2]), "r"(a[3]), "r"(b0), "r"(b1));
}

__device__ __forceinline__ uint32_t pack_hi(float x, float y) {
    return __byte_perm(__float_as_uint(x), __float_as_uint(y), 0x7632);
}
__device__ __forceinline__ uint32_t pack_lo(float x, float y) {
    float hx = __uint_as_float(__float_as_uint(x) & 0xFFFF0000u);
    float hy = __uint_as_float(__float_as_uint(y) & 0xFFFF0000u);
    __nv_bfloat162 t;
    t.x = __float2bfloat16(x - hx);
    t.y = __float2bfloat16(y - hy);
    return *reinterpret_cast<uint32_t*>(&t);
}

// ------------------------- cp.async helpers --------------------------------
__device__ __forceinline__ void cp16(uint32_t dst, const void* src) {
    asm volatile("cp.async.cg.shared.global [%0], [%1], 16;"
                 :: "r"(dst), "l"(src));
}
__device__ __forceinline__ void cp16z(uint32_t dst, const void* src, bool ok) {
    int b = ok ? 16 : 0;
    asm volatile("cp.async.cg.shared.global [%0], [%1], 16, %2;"
                 :: "r"(dst), "l"(src), "r"(b));
}
#define CP_COMMIT()  asm volatile("cp.async.commit_group;" ::: "memory")
#define CP_WAIT1()   asm volatile("cp.async.wait_group 1;" ::: "memory")
#define CP_WAIT0()   asm volatile("cp.async.wait_group 0;" ::: "memory")

// SMEM words per buffer: AH[128][20] AL[128][20] BH[16][136] BL[16][136]
static constexpr int W_AH = 0, W_AL = 2560, W_BH = 5120, W_BL = 7296;
static constexpr int WBUF = 9472;
static constexpr int SMEM_BYTES = 2 * WBUF * 4;        // 75776

__device__ __forceinline__ void cpA(uint32_t sb, const uint32_t* __restrict__ AH,
                                    const uint32_t* __restrict__ AL,
                                    int M, int rowBase, int c, int tid)
{
    #pragma unroll
    for (int t = 0; t < 4; t++) {
        int idx = tid + t * 256;          // 0..1023
        int r   = idx >> 3;
        int seg = idx & 7;                // 0..7 (0-3 hi, 4-7 lo)
        int row = rowBase + r;
        bool ok = row < M;
        int rowc = ok ? row : 0;
        int s4 = (seg & 3) * 4;
        const uint32_t* src = (seg < 4 ? AH : AL) + (size_t)rowc * 128 + c * 16 + s4;
        uint32_t dst = sb + ((seg < 4 ? W_AH : W_AL) + r * 20 + s4) * 4;
        cp16z(dst, src, ok);
    }
}

__device__ __forceinline__ void cpB(uint32_t sb, const uint32_t* __restrict__ WH,
                                    const uint32_t* __restrict__ WL,
                                    int colBase, int c, int tid)
{
    #pragma unroll
    for (int t = 0; t < 4; t++) {
        int idx  = tid + t * 256;         // 0..1023
        int kp   = idx >> 6;              // 0..15
        int rest = idx & 63;
        int arr  = rest >> 5;             // 0 hi, 1 lo
        int s4   = (rest & 31) * 4;
        const uint32_t* src = (arr ? WL : WH) + (size_t)(c * 16 + kp) * 256 + colBase + s4;
        uint32_t dst = sb + ((arr ? W_BL : W_BH) + kp * 136 + s4) * 4;
        cp16(dst, src);
    }
}

// ---------------------------------------------------------------------------
// mma GEMM (single branch): 256 threads, 8 warps (4m x 2n), warp tile 32x64.
// MODE 0: C fp32 = acc
// MODE 1: CH/CL split = pack(relu(acc+bias)+relu(agg+bagg))
// MODE 2: C fp32 = relu(acc+bias)
// ---------------------------------------------------------------------------
template<int MODE>
__global__ __launch_bounds__(256, 2)
void gemm_mma(const uint32_t* __restrict__ AH, const uint32_t* __restrict__ AL,
              const uint32_t* __restrict__ WH, const uint32_t* __restrict__ WL,
              const float* __restrict__ bias,
              const float* __restrict__ agg,
              const float* __restrict__ bagg,
              float* __restrict__ C,
              uint32_t* __restrict__ CH, uint32_t* __restrict__ CL,
              int M)
{
    extern __shared__ uint32_t sm[];
    const int tid  = threadIdx.x;
    const int lane = tid & 31;
    const int wid  = tid >> 5;
    const int wm   = wid & 3;
    const int wn   = wid >> 2;
    const int gid  = lane >> 2;
    const int tig  = lane & 3;
    const int rowBase = blockIdx.x * 128;
    const int colBase = blockIdx.y * 128;

    uint32_t sbase;
    {
        uint64_t a = __cvta_generic_to_shared(sm);
        sbase = (uint32_t)a;
    }

    float acc[2][8][4];
    #pragma unroll
    for (int mt = 0; mt < 2; mt++)
        #pragma unroll
        for (int nt = 0; nt < 8; nt++)
            #pragma unroll
            for (int q = 0; q < 4; q++) acc[mt][nt][q] = 0.f;

    cpA(sbase, AH, AL, M, rowBase, 0, tid);
    cpB(sbase, WH, WL, colBase, 0, tid);
    CP_COMMIT();

    #pragma unroll
    for (int c = 0; c < 8; c++) {
        if (c < 7) {
            uint32_t nb = sbase + ((c + 1) & 1) * WBUF * 4;
            cpA(nb, AH, AL, M, rowBase, c + 1, tid);
            cpB(nb, WH, WL, colBase, c + 1, tid);
            CP_COMMIT();
            CP_WAIT1();
        } else {
            CP_WAIT0();
        }
        __syncthreads();

        const uint32_t* buf = sm + (c & 1) * WBUF;
        const uint32_t* sAH = buf + W_AH;
        const uint32_t* sAL = buf + W_AL;
        const uint32_t* sBH = buf + W_BH;
        const uint32_t* sBL = buf + W_BL;

        #pragma unroll
        for (int ks = 0; ks < 2; ks++) {
            uint32_t aH[2][4], aL[2][4];
            #pragma unroll
            for (int mt = 0; mt < 2; mt++) {
                int off = (wm * 32 + mt * 16 + gid) * 20 + ks * 8 + tig;
                aH[mt][0] = sAH[off];       aH[mt][1] = sAH[off + 160];
                aH[mt][2] = sAH[off + 4];   aH[mt][3] = sAH[off + 164];
                aL[mt][0] = sAL[off];       aL[mt][1] = sAL[off + 160];
                aL[mt][2] = sAL[off + 4];   aL[mt][3] = sAL[off + 164];
            }
            #pragma unroll
            for (int nt = 0; nt < 8; nt++) {
                int bi = (ks * 8 + tig) * 136 + wn * 64 + nt * 8 + gid;
                uint32_t bh0 = sBH[bi], bh1 = sBH[bi + 544];
                uint32_t bl0 = sBL[bi], bl1 = sBL[bi + 544];
                #pragma unroll
                for (int mt = 0; mt < 2; mt++) {
                    mma16816(acc[mt][nt], aH[mt], bh0, bh1);
                    mma16816(acc[mt][nt], aH[mt], bl0, bl1);
                    mma16816(acc[mt][nt], aL[mt], bh0, bh1);
                }
            }
        }
        __syncthreads();
    }

    // ------------------------------ epilogue -------------------------------
    #pragma unroll
    for (int mt = 0; mt < 2; mt++) {
        #pragma unroll
        for (int nt = 0; nt < 8; nt++) {
            int r0  = rowBase + wm * 32 + mt * 16 + gid;
            int r1  = r0 + 8;
            int col = colBase + wn * 64 + nt * 8 + 2 * tig;
            float* a4 = acc[mt][nt];
            if (MODE == 0) {
                if (r0 < M)
                    *reinterpret_cast<float2*>(C + (size_t)r0 * 256 + col) =
                        make_float2(a4[0], a4[1]);
                if (r1 < M)
                    *reinterpret_cast<float2*>(C + (size_t)r1 * 256 + col) =
                        make_float2(a4[2], a4[3]);
            } else if (MODE == 1) {
                float2 bs = *reinterpret_cast<const float2*>(bias + col);
                float2 ba = *reinterpret_cast<const float2*>(bagg + col);
                if (r0 < M) {
                    float2 ag = *reinterpret_cast<const float2*>(agg + (size_t)r0 * 256 + col);
                    float v0 = frelu(a4[0] + bs.x) + frelu(ag.x + ba.x);
                    float v1 = frelu(a4[1] + bs.y) + frelu(ag.y + ba.y);
                    CH[(size_t)r0 * 128 + (col >> 1)] = pack_hi(v0, v1);
                    CL[(size_t)r0 * 128 + (col >> 1)] = pack_lo(v0, v1);
                }
                if (r1 < M) {
                    float2 ag = *reinterpret_cast<const float2*>(agg + (size_t)r1 * 256 + col);
                    float v0 = frelu(a4[2] + bs.x) + frelu(ag.x + ba.x);
                    float v1 = frelu(a4[3] + bs.y) + frelu(ag.y + ba.y);
                    CH[(size_t)r1 * 128 + (col >> 1)] = pack_hi(v0, v1);
                    CL[(size_t)r1 * 128 + (col >> 1)] = pack_lo(v0, v1);
                }
            } else {
                float2 bs = *reinterpret_cast<const float2*>(bias + col);
                if (r0 < M)
                    *reinterpret_cast<float2*>(C + (size_t)r0 * 256 + col) =
                        make_float2(frelu(a4[0] + bs.x), frelu(a4[1] + bs.y));
                if (r1 < M)
                    *reinterpret_cast<float2*>(C + (size_t)r1 * 256 + col) =
                        make_float2(frelu(a4[2] + bs.x), frelu(a4[3] + bs.y));
            }
        }
    }
}

// ---------------------------------------------------------------------------
// Conversion kernels
// ---------------------------------------------------------------------------
__global__ __launch_bounds__(256)
void conv_nf(const float* __restrict__ n1, const float* __restrict__ n2,
             uint32_t* __restrict__ H, uint32_t* __restrict__ L)
{
    size_t idx = (size_t)blockIdx.x * blockDim.x + threadIdx.x;
    if (idx >= 2 * (size_t)NW) return;
    int br = idx >= (size_t)NW;
    size_t w = idx - (size_t)br * NW;
    const float* nf = br ? n2 : n1;
    float2 v = *reinterpret_cast<const float2*>(nf + w * 2);
    H[idx] = pack_hi(v.x, v.y);
    L[idx] = pack_lo(v.x, v.y);
}

__global__ __launch_bounds__(256)
void conv_W(const float* __restrict__ m0, const float* __restrict__ m1,
            const float* __restrict__ m2, const float* __restrict__ m3,
            const float* __restrict__ m4, const float* __restrict__ m5,
            uint32_t* __restrict__ WH, uint32_t* __restrict__ WL)
{
    int idx = blockIdx.x * blockDim.x + threadIdx.x;
    if (idx >= 6 * 128 * 256) return;
    int m    = idx >> 15;
    int rest = idx & 32767;
    int k2   = rest >> 8;
    int n    = rest & 255;
    const float* Wm = (m == 0) ? m0 : (m == 1) ? m1 : (m == 2) ? m2
                    : (m == 3) ? m3 : (m == 4) ? m4 : m5;
    float a = Wm[(size_t)(2 * k2) * 256 + n];
    float b = Wm[(size_t)(2 * k2 + 1) * 256 + n];
    WH[idx] = pack_hi(a, b);
    WL[idx] = pack_lo(a, b);
}

// ---------------------------------------------------------------------------
// CSR build, both branches (on s2)
// ---------------------------------------------------------------------------
__global__ void hist_kernel(const int* __restrict__ dst1, const int* __restrict__ dst2,
                            int* __restrict__ deg)
{
    int idx = blockIdx.x * blockDim.x + threadIdx.x;
    if (idx < 2 * N_EDGES) {
        int br = idx >= N_EDGES;
        int e  = idx - br * N_EDGES;
        int d  = br ? dst2[e] : dst1[e];
        atomicAdd(&deg[br * N_NODES + d], 1);
    }
}

__global__ __launch_bounds__(256)
void scan1_kernel(const int* __restrict__ degAll, int* __restrict__ rowstartAll,
                  int* __restrict__ bsums)
{
    __shared__ int wsum[8];
    int br  = blockIdx.x / SCAN_BLKS;
    int blk = blockIdx.x % SCAN_BLKS;
    int t = threadIdx.x, lane = t & 31, w = t >> 5;
    const int* deg = degAll + br * N_NODES;
    int* rowstart  = rowstartAll + br * (N_NODES + 1);

    int base = blk * SCAN_CHUNK + t * 4;
    int v[4];
    #pragma unroll
    for (int i = 0; i < 4; i++)
        v[i] = (base + i < N_NODES) ? deg[base + i] : 0;
    int s = v[0] + v[1] + v[2] + v[3];

    int x = s;
    #pragma unroll
    for (int o = 1; o < 32; o <<= 1) {
        int n = __shfl_up_sync(0xFFFFFFFFu, x, o);
        if (lane >= o) x += n;
    }
    if (lane == 31) wsum[w] = x;
    __syncthreads();
    if (w == 0 && lane < 8) {
        int y = wsum[lane];
        #pragma unroll
        for (int o = 1; o < 8; o <<= 1) {
            int n = __shfl_up_sync(0xFFu, y, o);
            if (lane >= o) y += n;
        }
        wsum[lane] = y;
    }
    __syncthreads();
    int excl = x - s + (w > 0 ? wsum[w - 1] : 0);

    int run = excl;
    #pragma unroll
    for (int i = 0; i < 4; i++) {
        if (base + i < N_NODES) rowstart[base + i] = run;
        run += v[i];
    }
    if (t == 255) bsums[br * SCAN_BLKS + blk] = wsum[7];
}

__global__ __launch_bounds__(256)
void scan2_kernel(const int* __restrict__ bsums, int* __restrict__ rowstartAll,
                  int* __restrict__ cursorAll)
{
    __shared__ int soff;
    int br  = blockIdx.x / SCAN_BLKS;
    int blk = blockIdx.x % SCAN_BLKS;
    int t = threadIdx.x;
    int* rowstart = rowstartAll + br * (N_NODES + 1);
    int* cursor   = cursorAll   + br * N_NODES;

    if (t == 0) {
        int off = 0;
        for (int j = 0; j < blk; j++) off += bsums[br * SCAN_BLKS + j];
        soff = off;
        if (blockIdx.x == 0) {
            rowstartAll[N_NODES] = N_EDGES;
            rowstartAll[(N_NODES + 1) + N_NODES] = N_EDGES;
        }
    }
    __syncthreads();
    int off = soff;
    int base = blk * SCAN_CHUNK + t * 4;
    #pragma unroll
    for (int i = 0; i < 4; i++) {
        int g = base + i;
        if (g < N_NODES) {
            int val = rowstart[g] + off;
            rowstart[g] = val;
            cursor[g]   = val;
        }
    }
}

__global__ void fill_kernel(const int* __restrict__ src1, const int* __restrict__ dst1,
                            const int* __restrict__ src2, const int* __restrict__ dst2,
                            int* __restrict__ cursorAll, int* __restrict__ csrAll)
{
    int idx = blockIdx.x * blockDim.x + threadIdx.x;
    if (idx < 2 * N_EDGES) {
        int br = idx >= N_EDGES;
        int e  = idx - br * N_EDGES;
        int d  = br ? dst2[e] : dst1[e];
        int s  = br ? src2[e] : src1[e];
        int p  = atomicAdd(&cursorAll[br * N_NODES + d], 1);
        csrAll[br * N_EDGES + p] = s;
    }
}

// ---------------------------------------------------------------------------
// Warp-per-node gather of RAW features, emitting split-bf16 (hi/lo) output.
// hagg[n] = sum over in-edges of nf[src]; pack to aggH/aggL.
// ---------------------------------------------------------------------------
__global__ __launch_bounds__(256)
void gather_split(const float* __restrict__ nf,
                  const int* __restrict__ rowstart,
                  const int* __restrict__ csr,
                  uint32_t* __restrict__ aggH,
                  uint32_t* __restrict__ aggL)
{
    int node = (blockIdx.x * blockDim.x + threadIdx.x) >> 5;
    int lane = threadIdx.x & 31;
    if (node >= N_NODES) return;

    int beg = rowstart[node], end = rowstart[node + 1];
    float4 a0 = make_float4(0.f, 0.f, 0.f, 0.f);
    float4 a1 = make_float4(0.f, 0.f, 0.f, 0.f);
    float4 b0 = make_float4(0.f, 0.f, 0.f, 0.f);
    float4 b1 = make_float4(0.f, 0.f, 0.f, 0.f);
    int e = beg;
    for (; e + 1 < end; e += 2) {
        const float4* r0 = reinterpret_cast<const float4*>(nf + (size_t)csr[e]     * DFEAT);
        const float4* r1 = reinterpret_cast<const float4*>(nf + (size_t)csr[e + 1] * DFEAT);
        float4 u0 = r0[lane], u1 = r0[lane + 32];
        float4 v0 = r1[lane], v1 = r1[lane + 32];
        a0.x += u0.x; a0.y += u0.y; a0.z += u0.z; a0.w += u0.w;
        a1.x += u1.x; a1.y += u1.y; a1.z += u1.z; a1.w += u1.w;
        b0.x += v0.x; b0.y += v0.y; b0.z += v0.z; b0.w += v0.w;
        b1.x += v1.x; b1.y += v1.y; b1.z += v1.z; b1.w += v1.w;
    }
    if (e < end) {
        const float4* r0 = reinterpret_cast<const float4*>(nf + (size_t)csr[e] * DFEAT);
        float4 u0 = r0[lane], u1 = r0[lane + 32];
        a0.x += u0.x; a0.y += u0.y; a0.z += u0.z; a0.w += u0.w;
        a1.x += u1.x; a1.y += u1.y; a1.z += u1.z; a1.w += u1.w;
    }
    a0.x += b0.x; a0.y += b0.y; a0.z += b0.z; a0.w += b0.w;
    a1.x += b1.x; a1.y += b1.y; a1.z += b1.z; a1.w += b1.w;

    // pack: lane covers cols [4L,4L+3] (words 2L,2L+1) and [128+4L..] (words 64+2L..)
    size_t base = (size_t)node * 128;
    uint2 h0 = make_uint2(pack_hi(a0.x, a0.y), pack_hi(a0.z, a0.w));
    uint2 l0 = make_uint2(pack_lo(a0.x, a0.y), pack_lo(a0.z, a0.w));
    uint2 h1 = make_uint2(pack_hi(a1.x, a1.y), pack_hi(a1.z, a1.w));
    uint2 l1 = make_uint2(pack_lo(a1.x, a1.y), pack_lo(a1.z, a1.w));
    *reinterpret_cast<uint2*>(aggH + base + 2 * lane)      = h0;
    *reinterpret_cast<uint2*>(aggL + base + 2 * lane)      = l0;
    *reinterpret_cast<uint2*>(aggH + base + 64 + 2 * lane) = h1;
    *reinterpret_cast<uint2*>(aggL + base + 64 + 2 * lane) = l1;
}

// ---------------------------------------------------------------------------
// Segment sum (sorted gid), single branch
// ---------------------------------------------------------------------------
__global__ __launch_bounds__(256)
void segsum_kernel(const float* __restrict__ h2, const int* __restrict__ gid,
                   float* __restrict__ T, int* __restrict__ counts)
{
    __shared__ int sb, se;
    int g = blockIdx.x;
    if (threadIdx.x == 0) {
        int lo = 0, hi = N_NODES;
        while (lo < hi) { int m = (lo + hi) >> 1; if (gid[m] < g) lo = m + 1; else hi = m; }
        sb = lo;
        lo = sb; hi = N_NODES;
        while (lo < hi) { int m = (lo + hi) >> 1; if (gid[m] < g + 1) lo = m + 1; else hi = m; }
        se = lo;
        counts[g] = se - sb;
    }
    __syncthreads();
    int beg = sb, end = se, c = threadIdx.x;
    float s = 0.f;
    for (int r = beg; r < end; r++)
        s += h2[(size_t)r * DFEAT + c];
    T[(size_t)g * DFEAT + c] = s;
}

// ---------------------------------------------------------------------------
// Fused readout + predictor
// ---------------------------------------------------------------------------
__global__ __launch_bounds__(256)
void readout_final(const float* __restrict__ TAll, const int* __restrict__ countsAll,
                   const float* __restrict__ Ro1, const float* __restrict__ rbo1,
                   const float* __restrict__ Ro2, const float* __restrict__ rbo2,
                   const float* __restrict__ Wp, const float* __restrict__ bp,
                   float* __restrict__ out)
{
    __shared__ float ts1[DFEAT], ts2[DFEAT];
    __shared__ float red[256];
    int g = blockIdx.x;
    int t = threadIdx.x;
    ts1[t] = TAll[(size_t)g * DFEAT + t];
    ts2[t] = TAll[((size_t)N_GRAPHS + g) * DFEAT + t];
    __syncthreads();
    float c1 = (float)countsAll[g];
    float c2 = (float)countsAll[N_GRAPHS + g];
    float partial = 0.f;
    if (t < G_FEAT) {
        float s = c1 * rbo1[t] + c2 * rbo2[t];
        #pragma unroll 8
        for (int k = 0; k < DFEAT; k++)
            s += ts1[k] * Ro1[(size_t)k * G_FEAT + t]
               + ts2[k] * Ro2[(size_t)k * G_FEAT + t];
        partial = s * Wp[t];
    }
    red[t] = partial;
    __syncthreads();
    #pragma unroll
    for (int st = 128; st > 0; st >>= 1) {
        if (t < st) red[t] += red[t + st];
        __syncthreads();
    }
    if (t == 0) out[g] = red[0] + bp[0];
}

// ---------------------------------------------------------------------------
extern "C" void kernel_launch(void* const* d_in, const int* in_sizes, int n_in,
                              void* d_out, int out_size)
{
    const float* nf1 = (const float*)d_in[0];
    const float* nf2 = (const float*)d_in[2];
    const int* src1 = (const int*)d_in[4];
    const int* dst1 = (const int*)d_in[5];
    const int* gid1 = (const int*)d_in[6];
    const int* src2 = (const int*)d_in[7];
    const int* dst2 = (const int*)d_in[8];
    const int* gid2 = (const int*)d_in[9];
    const float* W1  = (const float*)d_in[10]; const float* b1  = (const float*)d_in[11];
    const float* Wr1 = (const float*)d_in[12]; const float* br1 = (const float*)d_in[13];
    const float* W2  = (const float*)d_in[14]; const float* b2  = (const float*)d_in[15];
    const float* Wr2 = (const float*)d_in[16]; const float* br2 = (const float*)d_in[17];
    const float* Ri1 = (const float*)d_in[18]; const float* rbi1 = (const float*)d_in[19];
    const float* Ro1 = (const float*)d_in[20]; const float* rbo1 = (const float*)d_in[21];
    const float* Ri2 = (const float*)d_in[22]; const float* rbi2 = (const float*)d_in[23];
    const float* Ro2 = (const float*)d_in[24]; const float* rbo2 = (const float*)d_in[25];
    const float* Wp  = (const float*)d_in[26]; const float* bp   = (const float*)d_in[27];

    float *t2, *T;
    uint32_t *aggH, *aggL, *nfH, *nfL, *h1H, *h1L, *WH, *WL;
    int *counts, *deg, *rowstart, *cursor, *csr_src, *bsums;
    cudaGetSymbolAddress((void**)&t2,       g_t2);
    cudaGetSymbolAddress((void**)&aggH,     g_aggH);
    cudaGetSymbolAddress((void**)&aggL,     g_aggL);
    cudaGetSymbolAddress((void**)&nfH,      g_nfH);
    cudaGetSymbolAddress((void**)&nfL,      g_nfL);
    cudaGetSymbolAddress((void**)&h1H,      g_h1H);
    cudaGetSymbolAddress((void**)&h1L,      g_h1L);
    cudaGetSymbolAddress((void**)&WH,       g_WH);
    cudaGetSymbolAddress((void**)&WL,       g_WL);
    cudaGetSymbolAddress((void**)&T,        g_T);
    cudaGetSymbolAddress((void**)&counts,   g_counts);
    cudaGetSymbolAddress((void**)&deg,      g_deg);
    cudaGetSymbolAddress((void**)&rowstart, g_rowstart);
    cudaGetSymbolAddress((void**)&cursor,   g_cursor);
    cudaGetSymbolAddress((void**)&csr_src,  g_csr_src);
    cudaGetSymbolAddress((void**)&bsums,    g_bsums);

    cudaFuncSetAttribute(gemm_mma<0>, cudaFuncAttributeMaxDynamicSharedMemorySize, SMEM_BYTES);
    cudaFuncSetAttribute(gemm_mma<1>, cudaFuncAttributeMaxDynamicSharedMemorySize, SMEM_BYTES);
    cudaFuncSetAttribute(gemm_mma<2>, cudaFuncAttributeMaxDynamicSharedMemorySize, SMEM_BYTES);

    // Lazy streams + events (created on the first, uncaptured, call).
    static cudaStream_t s_s2 = nullptr, s_s3 = nullptr;
    static cudaEvent_t  s_evF = nullptr, s_evConv = nullptr,
                        s_evG1 = nullptr, s_evG2 = nullptr, s_evJ3 = nullptr;
    static bool s_tried = false;
    if (!s_tried) {
        s_tried = true;
        bool ok =
            cudaStreamCreateWithFlags(&s_s2, cudaStreamNonBlocking) == cudaSuccess &&
            cudaStreamCreateWithFlags(&s_s3, cudaStreamNonBlocking) == cudaSuccess &&
            cudaEventCreateWithFlags(&s_evF,    cudaEventDisableTiming) == cudaSuccess &&
            cudaEventCreateWithFlags(&s_evConv, cudaEventDisableTiming) == cudaSuccess &&
            cudaEventCreateWithFlags(&s_evG1,   cudaEventDisableTiming) == cudaSuccess &&
            cudaEventCreateWithFlags(&s_evG2,   cudaEventDisableTiming) == cudaSuccess &&
            cudaEventCreateWithFlags(&s_evJ3,   cudaEventDisableTiming) == cudaSuccess;
        if (!ok) { s_s2 = nullptr; s_s3 = nullptr; }
    }
    const bool par = (s_s2 != nullptr);
    cudaStream_t s0 = (cudaStream_t)0;
    cudaStream_t s2 = par ? s_s2 : s0;
    cudaStream_t s3 = par ? s_s3 : s0;

    float* t2_1 = t2;   float* t2_2 = t2 + (size_t)N_NODES * DFEAT;
    float* T1   = T;    float* T2   = T  + (size_t)N_GRAPHS * DFEAT;
    int* counts1 = counts;  int* counts2 = counts + N_GRAPHS;
    uint32_t* aggH1 = aggH; uint32_t* aggH2 = aggH + (size_t)NW;
    uint32_t* aggL1 = aggL; uint32_t* aggL2 = aggL + (size_t)NW;
    uint32_t* nfH1 = nfH; uint32_t* nfH2 = nfH + (size_t)NW;
    uint32_t* nfL1 = nfL; uint32_t* nfL2 = nfL + (size_t)NW;
    uint32_t* h1H1 = h1H; uint32_t* h1H2 = h1H + (size_t)NW;
    uint32_t* h1L1 = h1L; uint32_t* h1L2 = h1L + (size_t)NW;
    const int* rs1 = rowstart;              const int* rs2 = rowstart + (N_NODES + 1);
    const int* cs1 = csr_src;               const int* cs2 = csr_src + N_EDGES;
    uint32_t* WH_ = WH;  uint32_t* WL_ = WL;
    const int WSZ = 128 * 256;   // slots: 0=W1 1=Wr1 2=Ri1 3=W2 4=Wr2 5=Ri2

    dim3 gemm_grid((N_NODES + 127) / 128, 2);       // per-branch: 391 x 2
    int eb2 = (2 * N_EDGES + 255) / 256;
    int gat_blocks = (N_NODES * 32 + 255) / 256;

    // ---- fork ----
    if (par) {
        cudaEventRecord(s_evF, s0);
        cudaStreamWaitEvent(s_s2, s_evF, 0);
        cudaStreamWaitEvent(s_s3, s_evF, 0);
    }

    // s2: CSR chain, then both raw-feature gathers (no GEMM dependency!)
    cudaMemsetAsync(deg, 0, 2 * N_NODES * sizeof(int), s2);
    hist_kernel<<<eb2, 256, 0, s2>>>(dst1, dst2, deg);
    scan1_kernel<<<2 * SCAN_BLKS, 256, 0, s2>>>(deg, rowstart, bsums);
    scan2_kernel<<<2 * SCAN_BLKS, 256, 0, s2>>>(bsums, rowstart, cursor);
    fill_kernel<<<eb2, 256, 0, s2>>>(src1, dst1, src2, dst2, cursor, csr_src);
    gather_split<<<gat_blocks, 256, 0, s2>>>(nf1, rs1, cs1, aggH1, aggL1);
    if (par) cudaEventRecord(s_evG1, s_s2);
    gather_split<<<gat_blocks, 256, 0, s2>>>(nf2, rs2, cs2, aggH2, aggL2);
    if (par) cudaEventRecord(s_evG2, s_s2);

    // s0: conversions, then branch-1 GEMM chain
    conv_nf<<<(int)((2 * (size_t)NW + 255) / 256), 256, 0, s0>>>(nf1, nf2, nfH, nfL);
    conv_W<<<(6 * 128 * 256 + 255) / 256, 256, 0, s0>>>(W1, Wr1, Ri1, W2, Wr2, Ri2,
                                                        WH, WL);
    if (par) cudaEventRecord(s_evConv, s0);

    // t2 = h @ Wr  (branch 1)
    gemm_mma<0><<<gemm_grid, 256, SMEM_BYTES, s0>>>(
        nfH1, nfL1, WH_ + 1 * WSZ, WL_ + 1 * WSZ,
        nullptr, nullptr, nullptr, t2_1, nullptr, nullptr, N_NODES);
    // h1 = relu(hagg@W + b) + relu(t2 + br)   (branch 1)
    if (par) cudaStreamWaitEvent(s0, s_evG1, 0);
    gemm_mma<1><<<gemm_grid, 256, SMEM_BYTES, s0>>>(
        aggH1, aggL1, WH_ + 0 * WSZ, WL_ + 0 * WSZ,
        b1, t2_1, br1, nullptr, h1H1, h1L1, N_NODES);
    // h2 = relu(h1@Ri + rbi)  (branch 1; overwrite t2_1)
    gemm_mma<2><<<gemm_grid, 256, SMEM_BYTES, s0>>>(
        h1H1, h1L1, WH_ + 2 * WSZ, WL_ + 2 * WSZ,
        rbi1, nullptr, nullptr, t2_1, nullptr, nullptr, N_NODES);
    segsum_kernel<<<N_GRAPHS, 256, 0, s0>>>(t2_1, gid1, T1, counts1);

    // s3: branch-2 GEMM chain
    if (par) cudaStreamWaitEvent(s_s3, s_evConv, 0);
    gemm_mma<0><<<gemm_grid, 256, SMEM_BYTES, s3>>>(
        nfH2, nfL2, WH_ + 4 * WSZ, WL_ + 4 * WSZ,
        nullptr, nullptr, nullptr, t2_2, nullptr, nullptr, N_NODES);
    if (par) cudaStreamWaitEvent(s_s3, s_evG2, 0);
    gemm_mma<1><<<gemm_grid, 256, SMEM_BYTES, s3>>>(
        aggH2, aggL2, WH_ + 3 * WSZ, WL_ + 3 * WSZ,
        b2, t2_2, br2, nullptr, h1H2, h1L2, N_NODES);
    gemm_mma<2><<<gemm_grid, 256, SMEM_BYTES, s3>>>(
        h1H2, h1L2, WH_ + 5 * WSZ, WL_ + 5 * WSZ,
        rbi2, nullptr, nullptr, t2_2, nullptr, nullptr, N_NODES);
    segsum_kernel<<<N_GRAPHS, 256, 0, s3>>>(t2_2, gid2, T2, counts2);
    if (par) cudaEventRecord(s_evJ3, s_s3);

    // join + fused readout/predictor
    if (par) cudaStreamWaitEvent(s0, s_evJ3, 0);
    readout_final<<<N_GRAPHS, 256, 0, s0>>>(T, counts, Ro1, rbo1, Ro2, rbo2, Wp, bp,
                                            (float*)d_out);
}

// round 12
// speedup vs baseline: 1.3999x; 1.3810x over previous
#include <cuda_runtime.h>
#include <cuda_fp16.h>
#include <cstdint>
#include <cstddef>

// ---------------------------------------------------------------------------
// mulGCN: two-branch GCN forward, fp16 mma.sync GEMMs (single precision-level,
// no hi/lo split: fp16's 11-bit mantissa gives ~2e-4/layer, inside 1e-3 gate)
// + cp.async double-buffered pipeline. Multi-block CSR scan.
// R12: 3x fewer MMAs than split-bf16. Structure/schedule = R11:
//   s2: CSR chain + raw-feature gathers (gather commutes with projection)
//   s0: conv + branch-1 GEMM chain;  s3: branch-2 GEMM chain
//   t2 = h@Wr; h1 = relu(hagg@W + b) + relu(t2 + br); h2 = relu(h1@Ri + rbi)
//   T[g] = segsum h2 (sorted gid); out = (T1@Ro1+c1 rbo1+T2@Ro2+c2 rbo2).Wp+bp
// ---------------------------------------------------------------------------

#define N_NODES   50000
#define N_EDGES   800000
#define DFEAT     256
#define G_FEAT    200
#define N_GRAPHS  512

#define NW   (N_NODES * 128)          // fp16-pair words per branch

#define SCAN_BLKS   49
#define SCAN_CHUNK  1024

__device__ float    g_t2  [2][(size_t)N_NODES * DFEAT];   // h@Wr; reused as h2
__device__ uint32_t g_aggQ[2][(size_t)NW];
__device__ uint32_t g_nfQ [2][(size_t)NW];
__device__ uint32_t g_h1Q [2][(size_t)NW];
__device__ uint32_t g_WQ  [6][128 * 256];   // k-major pairs: [kp][n]
__device__ float    g_T   [2][N_GRAPHS * DFEAT];
__device__ int      g_counts  [2][N_GRAPHS];
__device__ int      g_deg     [2][N_NODES];
__device__ int      g_rowstart[2][N_NODES + 1];
__device__ int      g_cursor  [2][N_NODES];
__device__ int      g_csr_src [2][N_EDGES];
__device__ int      g_bsums   [2 * SCAN_BLKS];

__device__ __forceinline__ float frelu(float x) { return x > 0.f ? x : 0.f; }

// ------------------------- mma / pack helpers ------------------------------
__device__ __forceinline__ void mma16816(float* c, const uint32_t* a,
                                         uint32_t b0, uint32_t b1) {
    asm volatile(
        "mma.sync.aligned.m16n8k16.row.col.f32.f16.f16.f32 "
        "{%0,%1,%2,%3}, {%4,%5,%6,%7}, {%8,%9}, {%0,%1,%2,%3};\n"
        : "+f"(c[0]), "+f"(c[1]), "+f"(c[2]), "+f"(c[3])
        : "r"(a[0]), "r"(a[1]), "r"(a[2]), "r"(a[3]), "r"(b0), "r"(b1));
}

__device__ __forceinline__ uint32_t pack_f16(float x, float y) {
    __half2 t;
    t.x = __float2half_rn(x);
    t.y = __float2half_rn(y);
    return *reinterpret_cast<uint32_t*>(&t);
}

// ------------------------- cp.async helpers --------------------------------
__device__ __forceinline__ void cp16(uint32_t dst, const void* src) {
    asm volatile("cp.async.cg.shared.global [%0], [%1], 16;"
                 :: "r"(dst), "l"(src));
}
__device__ __forceinline__ void cp16z(uint32_t dst, const void* src, bool ok) {
    int b = ok ? 16 : 0;
    asm volatile("cp.async.cg.shared.global [%0], [%1], 16, %2;"
                 :: "r"(dst), "l"(src), "r"(b));
}
#define CP_COMMIT()  asm volatile("cp.async.commit_group;" ::: "memory")
#define CP_WAIT1()   asm volatile("cp.async.wait_group 1;" ::: "memory")
#define CP_WAIT0()   asm volatile("cp.async.wait_group 0;" ::: "memory")

// SMEM words per buffer: A[128][20]  B[16][136]
static constexpr int W_A = 0, W_B = 2560;
static constexpr int WBUF = 4736;
static constexpr int SMEM_BYTES = 2 * WBUF * 4;        // 37888

__device__ __forceinline__ void cpA(uint32_t sb, const uint32_t* __restrict__ A,
                                    int M, int rowBase, int c, int tid)
{
    #pragma unroll
    for (int t = 0; t < 2; t++) {
        int idx = tid + t * 256;          // 0..511
        int r   = idx >> 2;
        int s4  = (idx & 3) * 4;
        int row = rowBase + r;
        bool ok = row < M;
        int rowc = ok ? row : 0;
        const uint32_t* src = A + (size_t)rowc * 128 + c * 16 + s4;
        uint32_t dst = sb + (W_A + r * 20 + s4) * 4;
        cp16z(dst, src, ok);
    }
}

__device__ __forceinline__ void cpB(uint32_t sb, const uint32_t* __restrict__ Wq,
                                    int colBase, int c, int tid)
{
    #pragma unroll
    for (int t = 0; t < 2; t++) {
        int idx = tid + t * 256;          // 0..511
        int kp  = idx >> 5;               // 0..15
        int n4  = (idx & 31) * 4;         // 0..124
        const uint32_t* src = Wq + (size_t)(c * 16 + kp) * 256 + colBase + n4;
        uint32_t dst = sb + (W_B + kp * 136 + n4) * 4;
        cp16(dst, src);
    }
}

// ---------------------------------------------------------------------------
// fp16 mma GEMM (single branch): 256 threads, 8 warps (4m x 2n), warp 32x64.
// MODE 0: C fp32 = acc
// MODE 1: CQ fp16-pack = relu(acc+bias) + relu(agg+bagg)
// MODE 2: C fp32 = relu(acc+bias)
// ---------------------------------------------------------------------------
template<int MODE>
__global__ __launch_bounds__(256, 2)
void gemm_mma(const uint32_t* __restrict__ A,
              const uint32_t* __restrict__ Wq,
              const float* __restrict__ bias,
              const float* __restrict__ agg,
              const float* __restrict__ bagg,
              float* __restrict__ C,
              uint32_t* __restrict__ CQ,
              int M)
{
    extern __shared__ uint32_t sm[];
    const int tid  = threadIdx.x;
    const int lane = tid & 31;
    const int wid  = tid >> 5;
    const int wm   = wid & 3;
    const int wn   = wid >> 2;
    const int gid  = lane >> 2;
    const int tig  = lane & 3;
    const int rowBase = blockIdx.x * 128;
    const int colBase = blockIdx.y * 128;

    uint32_t sbase;
    {
        uint64_t a = __cvta_generic_to_shared(sm);
        sbase = (uint32_t)a;
    }

    float acc[2][8][4];
    #pragma unroll
    for (int mt = 0; mt < 2; mt++)
        #pragma unroll
        for (int nt = 0; nt < 8; nt++)
            #pragma unroll
            for (int q = 0; q < 4; q++) acc[mt][nt][q] = 0.f;

    cpA(sbase, A, M, rowBase, 0, tid);
    cpB(sbase, Wq, colBase, 0, tid);
    CP_COMMIT();

    #pragma unroll
    for (int c = 0; c < 8; c++) {
        if (c < 7) {
            uint32_t nb = sbase + ((c + 1) & 1) * (WBUF * 4);
            cpA(nb, A, M, rowBase, c + 1, tid);
            cpB(nb, Wq, colBase, c + 1, tid);
            CP_COMMIT();
            CP_WAIT1();
        } else {
            CP_WAIT0();
        }
        __syncthreads();

        const uint32_t* buf = sm + (c & 1) * WBUF;
        const uint32_t* sA = buf + W_A;
        const uint32_t* sB = buf + W_B;

        #pragma unroll
        for (int ks = 0; ks < 2; ks++) {
            uint32_t a[2][4];
            #pragma unroll
            for (int mt = 0; mt < 2; mt++) {
                int off = (wm * 32 + mt * 16 + gid) * 20 + ks * 8 + tig;
                a[mt][0] = sA[off];       a[mt][1] = sA[off + 160];
                a[mt][2] = sA[off + 4];   a[mt][3] = sA[off + 164];
            }
            #pragma unroll
            for (int nt = 0; nt < 8; nt++) {
                int bi = (ks * 8 + tig) * 136 + wn * 64 + nt * 8 + gid;
                uint32_t b0 = sB[bi], b1 = sB[bi + 544];
                #pragma unroll
                for (int mt = 0; mt < 2; mt++)
                    mma16816(acc[mt][nt], a[mt], b0, b1);
            }
        }
        __syncthreads();
    }

    // ------------------------------ epilogue -------------------------------
    #pragma unroll
    for (int mt = 0; mt < 2; mt++) {
        #pragma unroll
        for (int nt = 0; nt < 8; nt++) {
            int r0  = rowBase + wm * 32 + mt * 16 + gid;
            int r1  = r0 + 8;
            int col = colBase + wn * 64 + nt * 8 + 2 * tig;
            float* a4 = acc[mt][nt];
            if (MODE == 0) {
                if (r0 < M)
                    *reinterpret_cast<float2*>(C + (size_t)r0 * 256 + col) =
                        make_float2(a4[0], a4[1]);
                if (r1 < M)
                    *reinterpret_cast<float2*>(C + (size_t)r1 * 256 + col) =
                        make_float2(a4[2], a4[3]);
            } else if (MODE == 1) {
                float2 bs = *reinterpret_cast<const float2*>(bias + col);
                float2 ba = *reinterpret_cast<const float2*>(bagg + col);
                if (r0 < M) {
                    float2 ag = *reinterpret_cast<const float2*>(agg + (size_t)r0 * 256 + col);
                    float v0 = frelu(a4[0] + bs.x) + frelu(ag.x + ba.x);
                    float v1 = frelu(a4[1] + bs.y) + frelu(ag.y + ba.y);
                    CQ[(size_t)r0 * 128 + (col >> 1)] = pack_f16(v0, v1);
                }
                if (r1 < M) {
                    float2 ag = *reinterpret_cast<const float2*>(agg + (size_t)r1 * 256 + col);
                    float v0 = frelu(a4[2] + bs.x) + frelu(ag.x + ba.x);
                    float v1 = frelu(a4[3] + bs.y) + frelu(ag.y + ba.y);
                    CQ[(size_t)r1 * 128 + (col >> 1)] = pack_f16(v0, v1);
                }
            } else {
                float2 bs = *reinterpret_cast<const float2*>(bias + col);
                if (r0 < M)
                    *reinterpret_cast<float2*>(C + (size_t)r0 * 256 + col) =
                        make_float2(frelu(a4[0] + bs.x), frelu(a4[1] + bs.y));
                if (r1 < M)
                    *reinterpret_cast<float2*>(C + (size_t)r1 * 256 + col) =
                        make_float2(frelu(a4[2] + bs.x), frelu(a4[3] + bs.y));
            }
        }
    }
}

// ---------------------------------------------------------------------------
// Conversion kernels (fp32 -> packed fp16)
// ---------------------------------------------------------------------------
__global__ __launch_bounds__(256)
void conv_nf(const float* __restrict__ n1, const float* __restrict__ n2,
             uint32_t* __restrict__ Q)
{
    size_t idx = (size_t)blockIdx.x * blockDim.x + threadIdx.x;
    if (idx >= 2 * (size_t)NW) return;
    int br = idx >= (size_t)NW;
    size_t w = idx - (size_t)br * NW;
    const float* nf = br ? n2 : n1;
    float2 v = *reinterpret_cast<const float2*>(nf + w * 2);
    Q[idx] = pack_f16(v.x, v.y);
}

// Weights k-major pairs: WQ[m][k2*256 + n] = f16x2(W[2k2][n], W[2k2+1][n])
__global__ __launch_bounds__(256)
void conv_W(const float* __restrict__ m0, const float* __restrict__ m1,
            const float* __restrict__ m2, const float* __restrict__ m3,
            const float* __restrict__ m4, const float* __restrict__ m5,
            uint32_t* __restrict__ WQ)
{
    int idx = blockIdx.x * blockDim.x + threadIdx.x;
    if (idx >= 6 * 128 * 256) return;
    int m    = idx >> 15;
    int rest = idx & 32767;
    int k2   = rest >> 8;
    int n    = rest & 255;
    const float* Wm = (m == 0) ? m0 : (m == 1) ? m1 : (m == 2) ? m2
                    : (m == 3) ? m3 : (m == 4) ? m4 : m5;
    float a = Wm[(size_t)(2 * k2) * 256 + n];
    float b = Wm[(size_t)(2 * k2 + 1) * 256 + n];
    WQ[idx] = pack_f16(a, b);
}

// ---------------------------------------------------------------------------
// CSR build, both branches (on s2)
// ---------------------------------------------------------------------------
__global__ void hist_kernel(const int* __restrict__ dst1, const int* __restrict__ dst2,
                            int* __restrict__ deg)
{
    int idx = blockIdx.x * blockDim.x + threadIdx.x;
    if (idx < 2 * N_EDGES) {
        int br = idx >= N_EDGES;
        int e  = idx - br * N_EDGES;
        int d  = br ? dst2[e] : dst1[e];
        atomicAdd(&deg[br * N_NODES + d], 1);
    }
}

__global__ __launch_bounds__(256)
void scan1_kernel(const int* __restrict__ degAll, int* __restrict__ rowstartAll,
                  int* __restrict__ bsums)
{
    __shared__ int wsum[8];
    int br  = blockIdx.x / SCAN_BLKS;
    int blk = blockIdx.x % SCAN_BLKS;
    int t = threadIdx.x, lane = t & 31, w = t >> 5;
    const int* deg = degAll + br * N_NODES;
    int* rowstart  = rowstartAll + br * (N_NODES + 1);

    int base = blk * SCAN_CHUNK + t * 4;
    int v[4];
    #pragma unroll
    for (int i = 0; i < 4; i++)
        v[i] = (base + i < N_NODES) ? deg[base + i] : 0;
    int s = v[0] + v[1] + v[2] + v[3];

    int x = s;
    #pragma unroll
    for (int o = 1; o < 32; o <<= 1) {
        int n = __shfl_up_sync(0xFFFFFFFFu, x, o);
        if (lane >= o) x += n;
    }
    if (lane == 31) wsum[w] = x;
    __syncthreads();
    if (w == 0 && lane < 8) {
        int y = wsum[lane];
        #pragma unroll
        for (int o = 1; o < 8; o <<= 1) {
            int n = __shfl_up_sync(0xFFu, y, o);
            if (lane >= o) y += n;
        }
        wsum[lane] = y;
    }
    __syncthreads();
    int excl = x - s + (w > 0 ? wsum[w - 1] : 0);

    int run = excl;
    #pragma unroll
    for (int i = 0; i < 4; i++) {
        if (base + i < N_NODES) rowstart[base + i] = run;
        run += v[i];
    }
    if (t == 255) bsums[br * SCAN_BLKS + blk] = wsum[7];
}

__global__ __launch_bounds__(256)
void scan2_kernel(const int* __restrict__ bsums, int* __restrict__ rowstartAll,
                  int* __restrict__ cursorAll)
{
    __shared__ int soff;
    int br  = blockIdx.x / SCAN_BLKS;
    int blk = blockIdx.x % SCAN_BLKS;
    int t = threadIdx.x;
    int* rowstart = rowstartAll + br * (N_NODES + 1);
    int* cursor   = cursorAll   + br * N_NODES;

    if (t == 0) {
        int off = 0;
        for (int j = 0; j < blk; j++) off += bsums[br * SCAN_BLKS + j];
        soff = off;
        if (blockIdx.x == 0) {
            rowstartAll[N_NODES] = N_EDGES;
            rowstartAll[(N_NODES + 1) + N_NODES] = N_EDGES;
        }
    }
    __syncthreads();
    int off = soff;
    int base = blk * SCAN_CHUNK + t * 4;
    #pragma unroll
    for (int i = 0; i < 4; i++) {
        int g = base + i;
        if (g < N_NODES) {
            int val = rowstart[g] + off;
            rowstart[g] = val;
            cursor[g]   = val;
        }
    }
}

__global__ void fill_kernel(const int* __restrict__ src1, const int* __restrict__ dst1,
                            const int* __restrict__ src2, const int* __restrict__ dst2,
                            int* __restrict__ cursorAll, int* __restrict__ csrAll)
{
    int idx = blockIdx.x * blockDim.x + threadIdx.x;
    if (idx < 2 * N_EDGES) {
        int br = idx >= N_EDGES;
        int e  = idx - br * N_EDGES;
        int d  = br ? dst2[e] : dst1[e];
        int s  = br ? src2[e] : src1[e];
        int p  = atomicAdd(&cursorAll[br * N_NODES + d], 1);
        csrAll[br * N_EDGES + p] = s;
    }
}

// ---------------------------------------------------------------------------
// Warp-per-node gather of RAW features, emitting packed fp16 output.
// hagg[n] = sum over in-edges of nf[src]  (fp32 accumulation)
// ---------------------------------------------------------------------------
__global__ __launch_bounds__(256)
void gather_split(const float* __restrict__ nf,
                  const int* __restrict__ rowstart,
                  const int* __restrict__ csr,
                  uint32_t* __restrict__ aggQ)
{
    int node = (blockIdx.x * blockDim.x + threadIdx.x) >> 5;
    int lane = threadIdx.x & 31;
    if (node >= N_NODES) return;

    int beg = rowstart[node], end = rowstart[node + 1];
    float4 a0 = make_float4(0.f, 0.f, 0.f, 0.f);
    float4 a1 = make_float4(0.f, 0.f, 0.f, 0.f);
    float4 b0 = make_float4(0.f, 0.f, 0.f, 0.f);
    float4 b1 = make_float4(0.f, 0.f, 0.f, 0.f);
    int e = beg;
    for (; e + 1 < end; e += 2) {
        const float4* r0 = reinterpret_cast<const float4*>(nf + (size_t)csr[e]     * DFEAT);
        const float4* r1 = reinterpret_cast<const float4*>(nf + (size_t)csr[e + 1] * DFEAT);
        float4 u0 = r0[lane], u1 = r0[lane + 32];
        float4 v0 = r1[lane], v1 = r1[lane + 32];
        a0.x += u0.x; a0.y += u0.y; a0.z += u0.z; a0.w += u0.w;
        a1.x += u1.x; a1.y += u1.y; a1.z += u1.z; a1.w += u1.w;
        b0.x += v0.x; b0.y += v0.y; b0.z += v0.z; b0.w += v0.w;
        b1.x += v1.x; b1.y += v1.y; b1.z += v1.z; b1.w += v1.w;
    }
    if (e < end) {
        const float4* r0 = reinterpret_cast<const float4*>(nf + (size_t)csr[e] * DFEAT);
        float4 u0 = r0[lane], u1 = r0[lane + 32];
        a0.x += u0.x; a0.y += u0.y; a0.z += u0.z; a0.w += u0.w;
        a1.x += u1.x; a1.y += u1.y; a1.z += u1.z; a1.w += u1.w;
    }
    a0.x += b0.x; a0.y += b0.y; a0.z += b0.z; a0.w += b0.w;
    a1.x += b1.x; a1.y += b1.y; a1.z += b1.z; a1.w += b1.w;

    size_t base = (size_t)node * 128;
    uint2 q0 = make_uint2(pack_f16(a0.x, a0.y), pack_f16(a0.z, a0.w));
    uint2 q1 = make_uint2(pack_f16(a1.x, a1.y), pack_f16(a1.z, a1.w));
    *reinterpret_cast<uint2*>(aggQ + base + 2 * lane)      = q0;
    *reinterpret_cast<uint2*>(aggQ + base + 64 + 2 * lane) = q1;
}

// ---------------------------------------------------------------------------
// Segment sum (sorted gid), single branch
// ---------------------------------------------------------------------------
__global__ __launch_bounds__(256)
void segsum_kernel(const float* __restrict__ h2, const int* __restrict__ gid,
                   float* __restrict__ T, int* __restrict__ counts)
{
    __shared__ int sb, se;
    int g = blockIdx.x;
    if (threadIdx.x == 0) {
        int lo = 0, hi = N_NODES;
        while (lo < hi) { int m = (lo + hi) >> 1; if (gid[m] < g) lo = m + 1; else hi = m; }
        sb = lo;
        lo = sb; hi = N_NODES;
        while (lo < hi) { int m = (lo + hi) >> 1; if (gid[m] < g + 1) lo = m + 1; else hi = m; }
        se = lo;
        counts[g] = se - sb;
    }
    __syncthreads();
    int beg = sb, end = se, c = threadIdx.x;
    float s = 0.f;
    for (int r = beg; r < end; r++)
        s += h2[(size_t)r * DFEAT + c];
    T[(size_t)g * DFEAT + c] = s;
}

// ---------------------------------------------------------------------------
// Fused readout + predictor
// ---------------------------------------------------------------------------
__global__ __launch_bounds__(256)
void readout_final(const float* __restrict__ TAll, const int* __restrict__ countsAll,
                   const float* __restrict__ Ro1, const float* __restrict__ rbo1,
                   const float* __restrict__ Ro2, const float* __restrict__ rbo2,
                   const float* __restrict__ Wp, const float* __restrict__ bp,
                   float* __restrict__ out)
{
    __shared__ float ts1[DFEAT], ts2[DFEAT];
    __shared__ float red[256];
    int g = blockIdx.x;
    int t = threadIdx.x;
    ts1[t] = TAll[(size_t)g * DFEAT + t];
    ts2[t] = TAll[((size_t)N_GRAPHS + g) * DFEAT + t];
    __syncthreads();
    float c1 = (float)countsAll[g];
    float c2 = (float)countsAll[N_GRAPHS + g];
    float partial = 0.f;
    if (t < G_FEAT) {
        float s = c1 * rbo1[t] + c2 * rbo2[t];
        #pragma unroll 8
        for (int k = 0; k < DFEAT; k++)
            s += ts1[k] * Ro1[(size_t)k * G_FEAT + t]
               + ts2[k] * Ro2[(size_t)k * G_FEAT + t];
        partial = s * Wp[t];
    }
    red[t] = partial;
    __syncthreads();
    #pragma unroll
    for (int st = 128; st > 0; st >>= 1) {
        if (t < st) red[t] += red[t + st];
        __syncthreads();
    }
    if (t == 0) out[g] = red[0] + bp[0];
}

// ---------------------------------------------------------------------------
extern "C" void kernel_launch(void* const* d_in, const int* in_sizes, int n_in,
                              void* d_out, int out_size)
{
    const float* nf1 = (const float*)d_in[0];
    const float* nf2 = (const float*)d_in[2];
    const int* src1 = (const int*)d_in[4];
    const int* dst1 = (const int*)d_in[5];
    const int* gid1 = (const int*)d_in[6];
    const int* src2 = (const int*)d_in[7];
    const int* dst2 = (const int*)d_in[8];
    const int* gid2 = (const int*)d_in[9];
    const float* W1  = (const float*)d_in[10]; const float* b1  = (const float*)d_in[11];
    const float* Wr1 = (const float*)d_in[12]; const float* br1 = (const float*)d_in[13];
    const float* W2  = (const float*)d_in[14]; const float* b2  = (const float*)d_in[15];
    const float* Wr2 = (const float*)d_in[16]; const float* br2 = (const float*)d_in[17];
    const float* Ri1 = (const float*)d_in[18]; const float* rbi1 = (const float*)d_in[19];
    const float* Ro1 = (const float*)d_in[20]; const float* rbo1 = (const float*)d_in[21];
    const float* Ri2 = (const float*)d_in[22]; const float* rbi2 = (const float*)d_in[23];
    const float* Ro2 = (const float*)d_in[24]; const float* rbo2 = (const float*)d_in[25];
    const float* Wp  = (const float*)d_in[26]; const float* bp   = (const float*)d_in[27];

    float *t2, *T;
    uint32_t *aggQ, *nfQ, *h1Q, *WQ;
    int *counts, *deg, *rowstart, *cursor, *csr_src, *bsums;
    cudaGetSymbolAddress((void**)&t2,       g_t2);
    cudaGetSymbolAddress((void**)&aggQ,     g_aggQ);
    cudaGetSymbolAddress((void**)&nfQ,      g_nfQ);
    cudaGetSymbolAddress((void**)&h1Q,      g_h1Q);
    cudaGetSymbolAddress((void**)&WQ,       g_WQ);
    cudaGetSymbolAddress((void**)&T,        g_T);
    cudaGetSymbolAddress((void**)&counts,   g_counts);
    cudaGetSymbolAddress((void**)&deg,      g_deg);
    cudaGetSymbolAddress((void**)&rowstart, g_rowstart);
    cudaGetSymbolAddress((void**)&cursor,   g_cursor);
    cudaGetSymbolAddress((void**)&csr_src,  g_csr_src);
    cudaGetSymbolAddress((void**)&bsums,    g_bsums);

    cudaFuncSetAttribute(gemm_mma<0>, cudaFuncAttributeMaxDynamicSharedMemorySize, SMEM_BYTES);
    cudaFuncSetAttribute(gemm_mma<1>, cudaFuncAttributeMaxDynamicSharedMemorySize, SMEM_BYTES);
    cudaFuncSetAttribute(gemm_mma<2>, cudaFuncAttributeMaxDynamicSharedMemorySize, SMEM_BYTES);

    // Lazy streams + events (created on the first, uncaptured, call).
    static cudaStream_t s_s2 = nullptr, s_s3 = nullptr;
    static cudaEvent_t  s_evF = nullptr, s_evConv = nullptr,
                        s_evG1 = nullptr, s_evG2 = nullptr, s_evJ3 = nullptr;
    static bool s_tried = false;
    if (!s_tried) {
        s_tried = true;
        bool ok =
            cudaStreamCreateWithFlags(&s_s2, cudaStreamNonBlocking) == cudaSuccess &&
            cudaStreamCreateWithFlags(&s_s3, cudaStreamNonBlocking) == cudaSuccess &&
            cudaEventCreateWithFlags(&s_evF,    cudaEventDisableTiming) == cudaSuccess &&
            cudaEventCreateWithFlags(&s_evConv, cudaEventDisableTiming) == cudaSuccess &&
            cudaEventCreateWithFlags(&s_evG1,   cudaEventDisableTiming) == cudaSuccess &&
            cudaEventCreateWithFlags(&s_evG2,   cudaEventDisableTiming) == cudaSuccess &&
            cudaEventCreateWithFlags(&s_evJ3,   cudaEventDisableTiming) == cudaSuccess;
        if (!ok) { s_s2 = nullptr; s_s3 = nullptr; }
    }
    const bool par = (s_s2 != nullptr);
    cudaStream_t s0 = (cudaStream_t)0;
    cudaStream_t s2 = par ? s_s2 : s0;
    cudaStream_t s3 = par ? s_s3 : s0;

    float* t2_1 = t2;   float* t2_2 = t2 + (size_t)N_NODES * DFEAT;
    float* T1   = T;    float* T2   = T  + (size_t)N_GRAPHS * DFEAT;
    int* counts1 = counts;  int* counts2 = counts + N_GRAPHS;
    uint32_t* aggQ1 = aggQ; uint32_t* aggQ2 = aggQ + (size_t)NW;
    uint32_t* nfQ1 = nfQ;   uint32_t* nfQ2 = nfQ + (size_t)NW;
    uint32_t* h1Q1 = h1Q;   uint32_t* h1Q2 = h1Q + (size_t)NW;
    const int* rs1 = rowstart;              const int* rs2 = rowstart + (N_NODES + 1);
    const int* cs1 = csr_src;               const int* cs2 = csr_src + N_EDGES;
    const int WSZ = 128 * 256;   // slots: 0=W1 1=Wr1 2=Ri1 3=W2 4=Wr2 5=Ri2

    dim3 gemm_grid((N_NODES + 127) / 128, 2);       // per-branch: 391 x 2
    int eb2 = (2 * N_EDGES + 255) / 256;
    int gat_blocks = (N_NODES * 32 + 255) / 256;

    // ---- fork ----
    if (par) {
        cudaEventRecord(s_evF, s0);
        cudaStreamWaitEvent(s_s2, s_evF, 0);
        cudaStreamWaitEvent(s_s3, s_evF, 0);
    }

    // s2: CSR chain, then both raw-feature gathers (no GEMM dependency)
    cudaMemsetAsync(deg, 0, 2 * N_NODES * sizeof(int), s2);
    hist_kernel<<<eb2, 256, 0, s2>>>(dst1, dst2, deg);
    scan1_kernel<<<2 * SCAN_BLKS, 256, 0, s2>>>(deg, rowstart, bsums);
    scan2_kernel<<<2 * SCAN_BLKS, 256, 0, s2>>>(bsums, rowstart, cursor);
    fill_kernel<<<eb2, 256, 0, s2>>>(src1, dst1, src2, dst2, cursor, csr_src);
    gather_split<<<gat_blocks, 256, 0, s2>>>(nf1, rs1, cs1, aggQ1);
    if (par) cudaEventRecord(s_evG1, s_s2);
    gather_split<<<gat_blocks, 256, 0, s2>>>(nf2, rs2, cs2, aggQ2);
    if (par) cudaEventRecord(s_evG2, s_s2);

    // s0: conversions, then branch-1 GEMM chain
    conv_nf<<<(int)((2 * (size_t)NW + 255) / 256), 256, 0, s0>>>(nf1, nf2, nfQ);
    conv_W<<<(6 * 128 * 256 + 255) / 256, 256, 0, s0>>>(W1, Wr1, Ri1, W2, Wr2, Ri2, WQ);
    if (par) cudaEventRecord(s_evConv, s0);

    // t2 = h @ Wr  (branch 1)
    gemm_mma<0><<<gemm_grid, 256, SMEM_BYTES, s0>>>(
        nfQ1, WQ + 1 * WSZ, nullptr, nullptr, nullptr, t2_1, nullptr, N_NODES);
    // h1 = relu(hagg@W + b) + relu(t2 + br)   (branch 1)
    if (par) cudaStreamWaitEvent(s0, s_evG1, 0);
    gemm_mma<1><<<gemm_grid, 256, SMEM_BYTES, s0>>>(
        aggQ1, WQ + 0 * WSZ, b1, t2_1, br1, nullptr, h1Q1, N_NODES);
    // h2 = relu(h1@Ri + rbi)  (branch 1; overwrite t2_1)
    gemm_mma<2><<<gemm_grid, 256, SMEM_BYTES, s0>>>(
        h1Q1, WQ + 2 * WSZ, rbi1, nullptr, nullptr, t2_1, nullptr, N_NODES);
    segsum_kernel<<<N_GRAPHS, 256, 0, s0>>>(t2_1, gid1, T1, counts1);

    // s3: branch-2 GEMM chain
    if (par) cudaStreamWaitEvent(s_s3, s_evConv, 0);
    gemm_mma<0><<<gemm_grid, 256, SMEM_BYTES, s3>>>(
        nfQ2, WQ + 4 * WSZ, nullptr, nullptr, nullptr, t2_2, nullptr, N_NODES);
    if (par) cudaStreamWaitEvent(s_s3, s_evG2, 0);
    gemm_mma<1><<<gemm_grid, 256, SMEM_BYTES, s3>>>(
        aggQ2, WQ + 3 * WSZ, b2, t2_2, br2, nullptr, h1Q2, N_NODES);
    gemm_mma<2><<<gemm_grid, 256, SMEM_BYTES, s3>>>(
        h1Q2, WQ + 5 * WSZ, rbi2, nullptr, nullptr, t2_2, nullptr, N_NODES);
    segsum_kernel<<<N_GRAPHS, 256, 0, s3>>>(t2_2, gid2, T2, counts2);
    if (par) cudaEventRecord(s_evJ3, s_s3);

    // join + fused readout/predictor
    if (par) cudaStreamWaitEvent(s0, s_evJ3, 0);
    readout_final<<<N_GRAPHS, 256, 0, s0>>>(T, counts, Ro1, rbo1, Ro2, rbo2, Wp, bp,
                                            (float*)d_out);
}

// round 13
// speedup vs baseline: 1.5153x; 1.0825x over previous
#include <cuda_runtime.h>
#include <cuda_fp16.h>
#include <cstdint>
#include <cstddef>

// ---------------------------------------------------------------------------
// mulGCN: two-branch GCN forward, fp16 mma.sync GEMMs + cp.async pipeline.
// R13: gather reads fp16-packed features (half the L2 traffic of fp32),
// fp32 accumulation, fp16 output. Schedule:
//   s0: conv_nf (evNF) -> conv_W (evConv) -> branch-1 GEMM chain
//   s2: CSR chain -> [wait evNF] gather1 (evG1) -> gather2 (evG2)
//   s3: [wait evConv] branch-2 GEMM chain
//   t2 = h@Wr; h1 = relu(hagg@W + b) + relu(t2 + br); h2 = relu(h1@Ri + rbi)
//   T[g] = segsum h2 (sorted gid); out = (T1@Ro1+c1 rbo1+T2@Ro2+c2 rbo2).Wp+bp
// ---------------------------------------------------------------------------

#define N_NODES   50000
#define N_EDGES   800000
#define DFEAT     256
#define G_FEAT    200
#define N_GRAPHS  512

#define NW   (N_NODES * 128)          // fp16-pair words per branch

#define SCAN_BLKS   49
#define SCAN_CHUNK  1024

__device__ float    g_t2  [2][(size_t)N_NODES * DFEAT];   // h@Wr; reused as h2
__device__ uint32_t g_aggQ[2][(size_t)NW];
__device__ uint32_t g_nfQ [2][(size_t)NW];
__device__ uint32_t g_h1Q [2][(size_t)NW];
__device__ uint32_t g_WQ  [6][128 * 256];   // k-major pairs: [kp][n]
__device__ float    g_T   [2][N_GRAPHS * DFEAT];
__device__ int      g_counts  [2][N_GRAPHS];
__device__ int      g_deg     [2][N_NODES];
__device__ int      g_rowstart[2][N_NODES + 1];
__device__ int      g_cursor  [2][N_NODES];
__device__ int      g_csr_src [2][N_EDGES];
__device__ int      g_bsums   [2 * SCAN_BLKS];

__device__ __forceinline__ float frelu(float x) { return x > 0.f ? x : 0.f; }

// ------------------------- mma / pack helpers ------------------------------
__device__ __forceinline__ void mma16816(float* c, const uint32_t* a,
                                         uint32_t b0, uint32_t b1) {
    asm volatile(
        "mma.sync.aligned.m16n8k16.row.col.f32.f16.f16.f32 "
        "{%0,%1,%2,%3}, {%4,%5,%6,%7}, {%8,%9}, {%0,%1,%2,%3};\n"
        : "+f"(c[0]), "+f"(c[1]), "+f"(c[2]), "+f"(c[3])
        : "r"(a[0]), "r"(a[1]), "r"(a[2]), "r"(a[3]), "r"(b0), "r"(b1));
}

__device__ __forceinline__ uint32_t pack_f16(float x, float y) {
    __half2 t;
    t.x = __float2half_rn(x);
    t.y = __float2half_rn(y);
    return *reinterpret_cast<uint32_t*>(&t);
}

// ------------------------- cp.async helpers --------------------------------
__device__ __forceinline__ void cp16(uint32_t dst, const void* src) {
    asm volatile("cp.async.cg.shared.global [%0], [%1], 16;"
                 :: "r"(dst), "l"(src));
}
__device__ __forceinline__ void cp16z(uint32_t dst, const void* src, bool ok) {
    int b = ok ? 16 : 0;
    asm volatile("cp.async.cg.shared.global [%0], [%1], 16, %2;"
                 :: "r"(dst), "l"(src), "r"(b));
}
#define CP_COMMIT()  asm volatile("cp.async.commit_group;" ::: "memory")
#define CP_WAIT1()   asm volatile("cp.async.wait_group 1;" ::: "memory")
#define CP_WAIT0()   asm volatile("cp.async.wait_group 0;" ::: "memory")

// SMEM words per buffer: A[128][20]  B[16][136]
static constexpr int W_A = 0, W_B = 2560;
static constexpr int WBUF = 4736;
static constexpr int SMEM_BYTES = 2 * WBUF * 4;        // 37888

__device__ __forceinline__ void cpA(uint32_t sb, const uint32_t* __restrict__ A,
                                    int M, int rowBase, int c, int tid)
{
    #pragma unroll
    for (int t = 0; t < 2; t++) {
        int idx = tid + t * 256;          // 0..511
        int r   = idx >> 2;
        int s4  = (idx & 3) * 4;
        int row = rowBase + r;
        bool ok = row < M;
        int rowc = ok ? row : 0;
        const uint32_t* src = A + (size_t)rowc * 128 + c * 16 + s4;
        uint32_t dst = sb + (W_A + r * 20 + s4) * 4;
        cp16z(dst, src, ok);
    }
}

__device__ __forceinline__ void cpB(uint32_t sb, const uint32_t* __restrict__ Wq,
                                    int colBase, int c, int tid)
{
    #pragma unroll
    for (int t = 0; t < 2; t++) {
        int idx = tid + t * 256;          // 0..511
        int kp  = idx >> 5;               // 0..15
        int n4  = (idx & 31) * 4;         // 0..124
        const uint32_t* src = Wq + (size_t)(c * 16 + kp) * 256 + colBase + n4;
        uint32_t dst = sb + (W_B + kp * 136 + n4) * 4;
        cp16(dst, src);
    }
}

// ---------------------------------------------------------------------------
// fp16 mma GEMM (single branch): 256 threads, 8 warps (4m x 2n), warp 32x64.
// MODE 0: C fp32 = acc
// MODE 1: CQ fp16-pack = relu(acc+bias) + relu(agg+bagg)
// MODE 2: C fp32 = relu(acc+bias)
// ---------------------------------------------------------------------------
template<int MODE>
__global__ __launch_bounds__(256, 2)
void gemm_mma(const uint32_t* __restrict__ A,
              const uint32_t* __restrict__ Wq,
              const float* __restrict__ bias,
              const float* __restrict__ agg,
              const float* __restrict__ bagg,
              float* __restrict__ C,
              uint32_t* __restrict__ CQ,
              int M)
{
    extern __shared__ uint32_t sm[];
    const int tid  = threadIdx.x;
    const int lane = tid & 31;
    const int wid  = tid >> 5;
    const int wm   = wid & 3;
    const int wn   = wid >> 2;
    const int gid  = lane >> 2;
    const int tig  = lane & 3;
    const int rowBase = blockIdx.x * 128;
    const int colBase = blockIdx.y * 128;

    uint32_t sbase;
    {
        uint64_t a = __cvta_generic_to_shared(sm);
        sbase = (uint32_t)a;
    }

    float acc[2][8][4];
    #pragma unroll
    for (int mt = 0; mt < 2; mt++)
        #pragma unroll
        for (int nt = 0; nt < 8; nt++)
            #pragma unroll
            for (int q = 0; q < 4; q++) acc[mt][nt][q] = 0.f;

    cpA(sbase, A, M, rowBase, 0, tid);
    cpB(sbase, Wq, colBase, 0, tid);
    CP_COMMIT();

    #pragma unroll
    for (int c = 0; c < 8; c++) {
        if (c < 7) {
            uint32_t nb = sbase + ((c + 1) & 1) * (WBUF * 4);
            cpA(nb, A, M, rowBase, c + 1, tid);
            cpB(nb, Wq, colBase, c + 1, tid);
            CP_COMMIT();
            CP_WAIT1();
        } else {
            CP_WAIT0();
        }
        __syncthreads();

        const uint32_t* buf = sm + (c & 1) * WBUF;
        const uint32_t* sA = buf + W_A;
        const uint32_t* sB = buf + W_B;

        #pragma unroll
        for (int ks = 0; ks < 2; ks++) {
            uint32_t a[2][4];
            #pragma unroll
            for (int mt = 0; mt < 2; mt++) {
                int off = (wm * 32 + mt * 16 + gid) * 20 + ks * 8 + tig;
                a[mt][0] = sA[off];       a[mt][1] = sA[off + 160];
                a[mt][2] = sA[off + 4];   a[mt][3] = sA[off + 164];
            }
            #pragma unroll
            for (int nt = 0; nt < 8; nt++) {
                int bi = (ks * 8 + tig) * 136 + wn * 64 + nt * 8 + gid;
                uint32_t b0 = sB[bi], b1 = sB[bi + 544];
                #pragma unroll
                for (int mt = 0; mt < 2; mt++)
                    mma16816(acc[mt][nt], a[mt], b0, b1);
            }
        }
        __syncthreads();
    }

    // ------------------------------ epilogue -------------------------------
    #pragma unroll
    for (int mt = 0; mt < 2; mt++) {
        #pragma unroll
        for (int nt = 0; nt < 8; nt++) {
            int r0  = rowBase + wm * 32 + mt * 16 + gid;
            int r1  = r0 + 8;
            int col = colBase + wn * 64 + nt * 8 + 2 * tig;
            float* a4 = acc[mt][nt];
            if (MODE == 0) {
                if (r0 < M)
                    *reinterpret_cast<float2*>(C + (size_t)r0 * 256 + col) =
                        make_float2(a4[0], a4[1]);
                if (r1 < M)
                    *reinterpret_cast<float2*>(C + (size_t)r1 * 256 + col) =
                        make_float2(a4[2], a4[3]);
            } else if (MODE == 1) {
                float2 bs = *reinterpret_cast<const float2*>(bias + col);
                float2 ba = *reinterpret_cast<const float2*>(bagg + col);
                if (r0 < M) {
                    float2 ag = *reinterpret_cast<const float2*>(agg + (size_t)r0 * 256 + col);
                    float v0 = frelu(a4[0] + bs.x) + frelu(ag.x + ba.x);
                    float v1 = frelu(a4[1] + bs.y) + frelu(ag.y + ba.y);
                    CQ[(size_t)r0 * 128 + (col >> 1)] = pack_f16(v0, v1);
                }
                if (r1 < M) {
                    float2 ag = *reinterpret_cast<const float2*>(agg + (size_t)r1 * 256 + col);
                    float v0 = frelu(a4[2] + bs.x) + frelu(ag.x + ba.x);
                    float v1 = frelu(a4[3] + bs.y) + frelu(ag.y + ba.y);
                    CQ[(size_t)r1 * 128 + (col >> 1)] = pack_f16(v0, v1);
                }
            } else {
                float2 bs = *reinterpret_cast<const float2*>(bias + col);
                if (r0 < M)
                    *reinterpret_cast<float2*>(C + (size_t)r0 * 256 + col) =
                        make_float2(frelu(a4[0] + bs.x), frelu(a4[1] + bs.y));
                if (r1 < M)
                    *reinterpret_cast<float2*>(C + (size_t)r1 * 256 + col) =
                        make_float2(frelu(a4[2] + bs.x), frelu(a4[3] + bs.y));
            }
        }
    }
}

// ---------------------------------------------------------------------------
// Conversion kernels (fp32 -> packed fp16)
// ---------------------------------------------------------------------------
__global__ __launch_bounds__(256)
void conv_nf(const float* __restrict__ n1, const float* __restrict__ n2,
             uint32_t* __restrict__ Q)
{
    size_t idx = (size_t)blockIdx.x * blockDim.x + threadIdx.x;
    if (idx >= 2 * (size_t)NW) return;
    int br = idx >= (size_t)NW;
    size_t w = idx - (size_t)br * NW;
    const float* nf = br ? n2 : n1;
    float2 v = *reinterpret_cast<const float2*>(nf + w * 2);
    Q[idx] = pack_f16(v.x, v.y);
}

__global__ __launch_bounds__(256)
void conv_W(const float* __restrict__ m0, const float* __restrict__ m1,
            const float* __restrict__ m2, const float* __restrict__ m3,
            const float* __restrict__ m4, const float* __restrict__ m5,
            uint32_t* __restrict__ WQ)
{
    int idx = blockIdx.x * blockDim.x + threadIdx.x;
    if (idx >= 6 * 128 * 256) return;
    int m    = idx >> 15;
    int rest = idx & 32767;
    int k2   = rest >> 8;
    int n    = rest & 255;
    const float* Wm = (m == 0) ? m0 : (m == 1) ? m1 : (m == 2) ? m2
                    : (m == 3) ? m3 : (m == 4) ? m4 : m5;
    float a = Wm[(size_t)(2 * k2) * 256 + n];
    float b = Wm[(size_t)(2 * k2 + 1) * 256 + n];
    WQ[idx] = pack_f16(a, b);
}

// ---------------------------------------------------------------------------
// CSR build, both branches (on s2)
// ---------------------------------------------------------------------------
__global__ void hist_kernel(const int* __restrict__ dst1, const int* __restrict__ dst2,
                            int* __restrict__ deg)
{
    int idx = blockIdx.x * blockDim.x + threadIdx.x;
    if (idx < 2 * N_EDGES) {
        int br = idx >= N_EDGES;
        int e  = idx - br * N_EDGES;
        int d  = br ? dst2[e] : dst1[e];
        atomicAdd(&deg[br * N_NODES + d], 1);
    }
}

__global__ __launch_bounds__(256)
void scan1_kernel(const int* __restrict__ degAll, int* __restrict__ rowstartAll,
                  int* __restrict__ bsums)
{
    __shared__ int wsum[8];
    int br  = blockIdx.x / SCAN_BLKS;
    int blk = blockIdx.x % SCAN_BLKS;
    int t = threadIdx.x, lane = t & 31, w = t >> 5;
    const int* deg = degAll + br * N_NODES;
    int* rowstart  = rowstartAll + br * (N_NODES + 1);

    int base = blk * SCAN_CHUNK + t * 4;
    int v[4];
    #pragma unroll
    for (int i = 0; i < 4; i++)
        v[i] = (base + i < N_NODES) ? deg[base + i] : 0;
    int s = v[0] + v[1] + v[2] + v[3];

    int x = s;
    #pragma unroll
    for (int o = 1; o < 32; o <<= 1) {
        int n = __shfl_up_sync(0xFFFFFFFFu, x, o);
        if (lane >= o) x += n;
    }
    if (lane == 31) wsum[w] = x;
    __syncthreads();
    if (w == 0 && lane < 8) {
        int y = wsum[lane];
        #pragma unroll
        for (int o = 1; o < 8; o <<= 1) {
            int n = __shfl_up_sync(0xFFu, y, o);
            if (lane >= o) y += n;
        }
        wsum[lane] = y;
    }
    __syncthreads();
    int excl = x - s + (w > 0 ? wsum[w - 1] : 0);

    int run = excl;
    #pragma unroll
    for (int i = 0; i < 4; i++) {
        if (base + i < N_NODES) rowstart[base + i] = run;
        run += v[i];
    }
    if (t == 255) bsums[br * SCAN_BLKS + blk] = wsum[7];
}

__global__ __launch_bounds__(256)
void scan2_kernel(const int* __restrict__ bsums, int* __restrict__ rowstartAll,
                  int* __restrict__ cursorAll)
{
    __shared__ int soff;
    int br  = blockIdx.x / SCAN_BLKS;
    int blk = blockIdx.x % SCAN_BLKS;
    int t = threadIdx.x;
    int* rowstart = rowstartAll + br * (N_NODES + 1);
    int* cursor   = cursorAll   + br * N_NODES;

    if (t == 0) {
        int off = 0;
        for (int j = 0; j < blk; j++) off += bsums[br * SCAN_BLKS + j];
        soff = off;
        if (blockIdx.x == 0) {
            rowstartAll[N_NODES] = N_EDGES;
            rowstartAll[(N_NODES + 1) + N_NODES] = N_EDGES;
        }
    }
    __syncthreads();
    int off = soff;
    int base = blk * SCAN_CHUNK + t * 4;
    #pragma unroll
    for (int i = 0; i < 4; i++) {
        int g = base + i;
        if (g < N_NODES) {
            int val = rowstart[g] + off;
            rowstart[g] = val;
            cursor[g]   = val;
        }
    }
}

__global__ void fill_kernel(const int* __restrict__ src1, const int* __restrict__ dst1,
                            const int* __restrict__ src2, const int* __restrict__ dst2,
                            int* __restrict__ cursorAll, int* __restrict__ csrAll)
{
    int idx = blockIdx.x * blockDim.x + threadIdx.x;
    if (idx < 2 * N_EDGES) {
        int br = idx >= N_EDGES;
        int e  = idx - br * N_EDGES;
        int d  = br ? dst2[e] : dst1[e];
        int s  = br ? src2[e] : src1[e];
        int p  = atomicAdd(&cursorAll[br * N_NODES + d], 1);
        csrAll[br * N_EDGES + p] = s;
    }
}

// ---------------------------------------------------------------------------
// Warp-per-node gather of fp16-packed features: one uint4 per lane per row.
// fp32 accumulation, fp16-packed output.
// ---------------------------------------------------------------------------
__global__ __launch_bounds__(256)
void gather_f16(const uint32_t* __restrict__ nfQ,
                const int* __restrict__ rowstart,
                const int* __restrict__ csr,
                uint32_t* __restrict__ aggQ)
{
    int node = (blockIdx.x * blockDim.x + threadIdx.x) >> 5;
    int lane = threadIdx.x & 31;
    if (node >= N_NODES) return;

    int beg = rowstart[node], end = rowstart[node + 1];
    float a[8];
    #pragma unroll
    for (int i = 0; i < 8; i++) a[i] = 0.f;
    float b[8];
    #pragma unroll
    for (int i = 0; i < 8; i++) b[i] = 0.f;

    int e = beg;
    for (; e + 1 < end; e += 2) {
        uint4 u = reinterpret_cast<const uint4*>(nfQ + (size_t)csr[e]     * 128)[lane];
        uint4 v = reinterpret_cast<const uint4*>(nfQ + (size_t)csr[e + 1] * 128)[lane];
        float2 f;
        f = __half22float2(*reinterpret_cast<__half2*>(&u.x)); a[0] += f.x; a[1] += f.y;
        f = __half22float2(*reinterpret_cast<__half2*>(&u.y)); a[2] += f.x; a[3] += f.y;
        f = __half22float2(*reinterpret_cast<__half2*>(&u.z)); a[4] += f.x; a[5] += f.y;
        f = __half22float2(*reinterpret_cast<__half2*>(&u.w)); a[6] += f.x; a[7] += f.y;
        f = __half22float2(*reinterpret_cast<__half2*>(&v.x)); b[0] += f.x; b[1] += f.y;
        f = __half22float2(*reinterpret_cast<__half2*>(&v.y)); b[2] += f.x; b[3] += f.y;
        f = __half22float2(*reinterpret_cast<__half2*>(&v.z)); b[4] += f.x; b[5] += f.y;
        f = __half22float2(*reinterpret_cast<__half2*>(&v.w)); b[6] += f.x; b[7] += f.y;
    }
    if (e < end) {
        uint4 u = reinterpret_cast<const uint4*>(nfQ + (size_t)csr[e] * 128)[lane];
        float2 f;
        f = __half22float2(*reinterpret_cast<__half2*>(&u.x)); a[0] += f.x; a[1] += f.y;
        f = __half22float2(*reinterpret_cast<__half2*>(&u.y)); a[2] += f.x; a[3] += f.y;
        f = __half22float2(*reinterpret_cast<__half2*>(&u.z)); a[4] += f.x; a[5] += f.y;
        f = __half22float2(*reinterpret_cast<__half2*>(&u.w)); a[6] += f.x; a[7] += f.y;
    }
    #pragma unroll
    for (int i = 0; i < 8; i++) a[i] += b[i];

    uint4 o;
    o.x = pack_f16(a[0], a[1]);
    o.y = pack_f16(a[2], a[3]);
    o.z = pack_f16(a[4], a[5]);
    o.w = pack_f16(a[6], a[7]);
    reinterpret_cast<uint4*>(aggQ + (size_t)node * 128)[lane] = o;
}

// ---------------------------------------------------------------------------
// Segment sum (sorted gid), single branch
// ---------------------------------------------------------------------------
__global__ __launch_bounds__(256)
void segsum_kernel(const float* __restrict__ h2, const int* __restrict__ gid,
                   float* __restrict__ T, int* __restrict__ counts)
{
    __shared__ int sb, se;
    int g = blockIdx.x;
    if (threadIdx.x == 0) {
        int lo = 0, hi = N_NODES;
        while (lo < hi) { int m = (lo + hi) >> 1; if (gid[m] < g) lo = m + 1; else hi = m; }
        sb = lo;
        lo = sb; hi = N_NODES;
        while (lo < hi) { int m = (lo + hi) >> 1; if (gid[m] < g + 1) lo = m + 1; else hi = m; }
        se = lo;
        counts[g] = se - sb;
    }
    __syncthreads();
    int beg = sb, end = se, c = threadIdx.x;
    float s = 0.f;
    for (int r = beg; r < end; r++)
        s += h2[(size_t)r * DFEAT + c];
    T[(size_t)g * DFEAT + c] = s;
}

// ---------------------------------------------------------------------------
// Fused readout + predictor
// ---------------------------------------------------------------------------
__global__ __launch_bounds__(256)
void readout_final(const float* __restrict__ TAll, const int* __restrict__ countsAll,
                   const float* __restrict__ Ro1, const float* __restrict__ rbo1,
                   const float* __restrict__ Ro2, const float* __restrict__ rbo2,
                   const float* __restrict__ Wp, const float* __restrict__ bp,
                   float* __restrict__ out)
{
    __shared__ float ts1[DFEAT], ts2[DFEAT];
    __shared__ float red[256];
    int g = blockIdx.x;
    int t = threadIdx.x;
    ts1[t] = TAll[(size_t)g * DFEAT + t];
    ts2[t] = TAll[((size_t)N_GRAPHS + g) * DFEAT + t];
    __syncthreads();
    float c1 = (float)countsAll[g];
    float c2 = (float)countsAll[N_GRAPHS + g];
    float partial = 0.f;
    if (t < G_FEAT) {
        float s = c1 * rbo1[t] + c2 * rbo2[t];
        #pragma unroll 8
        for (int k = 0; k < DFEAT; k++)
            s += ts1[k] * Ro1[(size_t)k * G_FEAT + t]
               + ts2[k] * Ro2[(size_t)k * G_FEAT + t];
        partial = s * Wp[t];
    }
    red[t] = partial;
    __syncthreads();
    #pragma unroll
    for (int st = 128; st > 0; st >>= 1) {
        if (t < st) red[t] += red[t + st];
        __syncthreads();
    }
    if (t == 0) out[g] = red[0] + bp[0];
}

// ---------------------------------------------------------------------------
extern "C" void kernel_launch(void* const* d_in, const int* in_sizes, int n_in,
                              void* d_out, int out_size)
{
    const float* nf1 = (const float*)d_in[0];
    const float* nf2 = (const float*)d_in[2];
    const int* src1 = (const int*)d_in[4];
    const int* dst1 = (const int*)d_in[5];
    const int* gid1 = (const int*)d_in[6];
    const int* src2 = (const int*)d_in[7];
    const int* dst2 = (const int*)d_in[8];
    const int* gid2 = (const int*)d_in[9];
    const float* W1  = (const float*)d_in[10]; const float* b1  = (const float*)d_in[11];
    const float* Wr1 = (const float*)d_in[12]; const float* br1 = (const float*)d_in[13];
    const float* W2  = (const float*)d_in[14]; const float* b2  = (const float*)d_in[15];
    const float* Wr2 = (const float*)d_in[16]; const float* br2 = (const float*)d_in[17];
    const float* Ri1 = (const float*)d_in[18]; const float* rbi1 = (const float*)d_in[19];
    const float* Ro1 = (const float*)d_in[20]; const float* rbo1 = (const float*)d_in[21];
    const float* Ri2 = (const float*)d_in[22]; const float* rbi2 = (const float*)d_in[23];
    const float* Ro2 = (const float*)d_in[24]; const float* rbo2 = (const float*)d_in[25];
    const float* Wp  = (const float*)d_in[26]; const float* bp   = (const float*)d_in[27];

    float *t2, *T;
    uint32_t *aggQ, *nfQ, *h1Q, *WQ;
    int *counts, *deg, *rowstart, *cursor, *csr_src, *bsums;
    cudaGetSymbolAddress((void**)&t2,       g_t2);
    cudaGetSymbolAddress((void**)&aggQ,     g_aggQ);
    cudaGetSymbolAddress((void**)&nfQ,      g_nfQ);
    cudaGetSymbolAddress((void**)&h1Q,      g_h1Q);
    cudaGetSymbolAddress((void**)&WQ,       g_WQ);
    cudaGetSymbolAddress((void**)&T,        g_T);
    cudaGetSymbolAddress((void**)&counts,   g_counts);
    cudaGetSymbolAddress((void**)&deg,      g_deg);
    cudaGetSymbolAddress((void**)&rowstart, g_rowstart);
    cudaGetSymbolAddress((void**)&cursor,   g_cursor);
    cudaGetSymbolAddress((void**)&csr_src,  g_csr_src);
    cudaGetSymbolAddress((void**)&bsums,    g_bsums);

    cudaFuncSetAttribute(gemm_mma<0>, cudaFuncAttributeMaxDynamicSharedMemorySize, SMEM_BYTES);
    cudaFuncSetAttribute(gemm_mma<1>, cudaFuncAttributeMaxDynamicSharedMemorySize, SMEM_BYTES);
    cudaFuncSetAttribute(gemm_mma<2>, cudaFuncAttributeMaxDynamicSharedMemorySize, SMEM_BYTES);

    // Lazy streams + events (created on the first, uncaptured, call).
    static cudaStream_t s_s2 = nullptr, s_s3 = nullptr;
    static cudaEvent_t  s_evF = nullptr, s_evNF = nullptr, s_evConv = nullptr,
                        s_evG1 = nullptr, s_evG2 = nullptr, s_evJ3 = nullptr;
    static bool s_tried = false;
    if (!s_tried) {
        s_tried = true;
        bool ok =
            cudaStreamCreateWithFlags(&s_s2, cudaStreamNonBlocking) == cudaSuccess &&
            cudaStreamCreateWithFlags(&s_s3, cudaStreamNonBlocking) == cudaSuccess &&
            cudaEventCreateWithFlags(&s_evF,    cudaEventDisableTiming) == cudaSuccess &&
            cudaEventCreateWithFlags(&s_evNF,   cudaEventDisableTiming) == cudaSuccess &&
            cudaEventCreateWithFlags(&s_evConv, cudaEventDisableTiming) == cudaSuccess &&
            cudaEventCreateWithFlags(&s_evG1,   cudaEventDisableTiming) == cudaSuccess &&
            cudaEventCreateWithFlags(&s_evG2,   cudaEventDisableTiming) == cudaSuccess &&
            cudaEventCreateWithFlags(&s_evJ3,   cudaEventDisableTiming) == cudaSuccess;
        if (!ok) { s_s2 = nullptr; s_s3 = nullptr; }
    }
    const bool par = (s_s2 != nullptr);
    cudaStream_t s0 = (cudaStream_t)0;
    cudaStream_t s2 = par ? s_s2 : s0;
    cudaStream_t s3 = par ? s_s3 : s0;

    float* t2_1 = t2;   float* t2_2 = t2 + (size_t)N_NODES * DFEAT;
    float* T1   = T;    float* T2   = T  + (size_t)N_GRAPHS * DFEAT;
    int* counts1 = counts;  int* counts2 = counts + N_GRAPHS;
    uint32_t* aggQ1 = aggQ; uint32_t* aggQ2 = aggQ + (size_t)NW;
    uint32_t* nfQ1 = nfQ;   uint32_t* nfQ2 = nfQ + (size_t)NW;
    uint32_t* h1Q1 = h1Q;   uint32_t* h1Q2 = h1Q + (size_t)NW;
    const int* rs1 = rowstart;              const int* rs2 = rowstart + (N_NODES + 1);
    const int* cs1 = csr_src;               const int* cs2 = csr_src + N_EDGES;
    const int WSZ = 128 * 256;   // slots: 0=W1 1=Wr1 2=Ri1 3=W2 4=Wr2 5=Ri2

    dim3 gemm_grid((N_NODES + 127) / 128, 2);       // per-branch: 391 x 2
    int eb2 = (2 * N_EDGES + 255) / 256;
    int gat_blocks = (N_NODES * 32 + 255) / 256;

    // ---- fork ----
    if (par) {
        cudaEventRecord(s_evF, s0);
        cudaStreamWaitEvent(s_s2, s_evF, 0);
        cudaStreamWaitEvent(s_s3, s_evF, 0);
    }

    // s0: conversions first (gathers depend on conv_nf)
    conv_nf<<<(int)((2 * (size_t)NW + 255) / 256), 256, 0, s0>>>(nf1, nf2, nfQ);
    if (par) cudaEventRecord(s_evNF, s0);
    conv_W<<<(6 * 128 * 256 + 255) / 256, 256, 0, s0>>>(W1, Wr1, Ri1, W2, Wr2, Ri2, WQ);
    if (par) cudaEventRecord(s_evConv, s0);

    // s2: CSR chain, then both fp16 gathers (wait conv_nf)
    cudaMemsetAsync(deg, 0, 2 * N_NODES * sizeof(int), s2);
    hist_kernel<<<eb2, 256, 0, s2>>>(dst1, dst2, deg);
    scan1_kernel<<<2 * SCAN_BLKS, 256, 0, s2>>>(deg, rowstart, bsums);
    scan2_kernel<<<2 * SCAN_BLKS, 256, 0, s2>>>(bsums, rowstart, cursor);
    fill_kernel<<<eb2, 256, 0, s2>>>(src1, dst1, src2, dst2, cursor, csr_src);
    if (par) cudaStreamWaitEvent(s_s2, s_evNF, 0);
    gather_f16<<<gat_blocks, 256, 0, s2>>>(nfQ1, rs1, cs1, aggQ1);
    if (par) cudaEventRecord(s_evG1, s_s2);
    gather_f16<<<gat_blocks, 256, 0, s2>>>(nfQ2, rs2, cs2, aggQ2);
    if (par) cudaEventRecord(s_evG2, s_s2);

    // s0: branch-1 GEMM chain
    // t2 = h @ Wr  (branch 1)
    gemm_mma<0><<<gemm_grid, 256, SMEM_BYTES, s0>>>(
        nfQ1, WQ + 1 * WSZ, nullptr, nullptr, nullptr, t2_1, nullptr, N_NODES);
    // h1 = relu(hagg@W + b) + relu(t2 + br)
    if (par) cudaStreamWaitEvent(s0, s_evG1, 0);
    gemm_mma<1><<<gemm_grid, 256, SMEM_BYTES, s0>>>(
        aggQ1, WQ + 0 * WSZ, b1, t2_1, br1, nullptr, h1Q1, N_NODES);
    // h2 = relu(h1@Ri + rbi)  (overwrite t2_1)
    gemm_mma<2><<<gemm_grid, 256, SMEM_BYTES, s0>>>(
        h1Q1, WQ + 2 * WSZ, rbi1, nullptr, nullptr, t2_1, nullptr, N_NODES);
    segsum_kernel<<<N_GRAPHS, 256, 0, s0>>>(t2_1, gid1, T1, counts1);

    // s3: branch-2 GEMM chain
    if (par) cudaStreamWaitEvent(s_s3, s_evConv, 0);
    gemm_mma<0><<<gemm_grid, 256, SMEM_BYTES, s3>>>(
        nfQ2, WQ + 4 * WSZ, nullptr, nullptr, nullptr, t2_2, nullptr, N_NODES);
    if (par) cudaStreamWaitEvent(s_s3, s_evG2, 0);
    gemm_mma<1><<<gemm_grid, 256, SMEM_BYTES, s3>>>(
        aggQ2, WQ + 3 * WSZ, b2, t2_2, br2, nullptr, h1Q2, N_NODES);
    gemm_mma<2><<<gemm_grid, 256, SMEM_BYTES, s3>>>(
        h1Q2, WQ + 5 * WSZ, rbi2, nullptr, nullptr, t2_2, nullptr, N_NODES);
    segsum_kernel<<<N_GRAPHS, 256, 0, s3>>>(t2_2, gid2, T2, counts2);
    if (par) cudaEventRecord(s_evJ3, s_s3);

    // join + fused readout/predictor
    if (par) cudaStreamWaitEvent(s0, s_evJ3, 0);
    readout_final<<<N_GRAPHS, 256, 0, s0>>>(T, counts, Ro1, rbo1, Ro2, rbo2, Wp, bp,
                                            (float*)d_out);
}

// round 14
// speedup vs baseline: 1.5310x; 1.0103x over previous
#include <cuda_runtime.h>
#include <cuda_fp16.h>
#include <cstdint>
#include <cstddef>

// ---------------------------------------------------------------------------
// mulGCN: two-branch GCN forward, fp16 mma.sync GEMMs + 4-stage cp.async
// pipeline (prefetch distance 3 hides L2/DRAM latency over the small fp16
// per-chunk compute). fp16 gather (half L2 traffic), fp32 accumulation.
// Schedule:
//   s0: conv_nf (evNF) -> conv_W (evConv) -> branch-1 GEMM chain
//   s2: CSR chain -> [wait evNF] gather1 (evG1) -> gather2 (evG2)
//   s3: [wait evConv] branch-2 GEMM chain
//   t2 = h@Wr; h1 = relu(hagg@W + b) + relu(t2 + br); h2 = relu(h1@Ri + rbi)
//   T[g] = segsum h2 (sorted gid); out = (T1@Ro1+c1 rbo1+T2@Ro2+c2 rbo2).Wp+bp
// ---------------------------------------------------------------------------

#define N_NODES   50000
#define N_EDGES   800000
#define DFEAT     256
#define G_FEAT    200
#define N_GRAPHS  512

#define NW   (N_NODES * 128)          // fp16-pair words per branch

#define SCAN_BLKS   49
#define SCAN_CHUNK  1024

__device__ float    g_t2  [2][(size_t)N_NODES * DFEAT];   // h@Wr; reused as h2
__device__ uint32_t g_aggQ[2][(size_t)NW];
__device__ uint32_t g_nfQ [2][(size_t)NW];
__device__ uint32_t g_h1Q [2][(size_t)NW];
__device__ uint32_t g_WQ  [6][128 * 256];   // k-major pairs: [kp][n]
__device__ float    g_T   [2][N_GRAPHS * DFEAT];
__device__ int      g_counts  [2][N_GRAPHS];
__device__ int      g_deg     [2][N_NODES];
__device__ int      g_rowstart[2][N_NODES + 1];
__device__ int      g_cursor  [2][N_NODES];
__device__ int      g_csr_src [2][N_EDGES];
__device__ int      g_bsums   [2 * SCAN_BLKS];

__device__ __forceinline__ float frelu(float x) { return x > 0.f ? x : 0.f; }

// ------------------------- mma / pack helpers ------------------------------
__device__ __forceinline__ void mma16816(float* c, const uint32_t* a,
                                         uint32_t b0, uint32_t b1) {
    asm volatile(
        "mma.sync.aligned.m16n8k16.row.col.f32.f16.f16.f32 "
        "{%0,%1,%2,%3}, {%4,%5,%6,%7}, {%8,%9}, {%0,%1,%2,%3};\n"
        : "+f"(c[0]), "+f"(c[1]), "+f"(c[2]), "+f"(c[3])
        : "r"(a[0]), "r"(a[1]), "r"(a[2]), "r"(a[3]), "r"(b0), "r"(b1));
}

__device__ __forceinline__ uint32_t pack_f16(float x, float y) {
    __half2 t;
    t.x = __float2half_rn(x);
    t.y = __float2half_rn(y);
    return *reinterpret_cast<uint32_t*>(&t);
}

// ------------------------- cp.async helpers --------------------------------
__device__ __forceinline__ void cp16(uint32_t dst, const void* src) {
    asm volatile("cp.async.cg.shared.global [%0], [%1], 16;"
                 :: "r"(dst), "l"(src));
}
__device__ __forceinline__ void cp16z(uint32_t dst, const void* src, bool ok) {
    int b = ok ? 16 : 0;
    asm volatile("cp.async.cg.shared.global [%0], [%1], 16, %2;"
                 :: "r"(dst), "l"(src), "r"(b));
}
#define CP_COMMIT()  asm volatile("cp.async.commit_group;" ::: "memory")
#define CP_WAIT(n)   asm volatile("cp.async.wait_group %0;" :: "n"(n) : "memory")

// SMEM words per buffer: A[128][20]  B[16][136]; 4 buffers
static constexpr int W_A = 0, W_B = 2560;
static constexpr int WBUF = 4736;
static constexpr int N_STAGE = 4;
static constexpr int SMEM_BYTES = N_STAGE * WBUF * 4;   // 75776

__device__ __forceinline__ void cpA(uint32_t sb, const uint32_t* __restrict__ A,
                                    int M, int rowBase, int c, int tid)
{
    #pragma unroll
    for (int t = 0; t < 2; t++) {
        int idx = tid + t * 256;          // 0..511
        int r   = idx >> 2;
        int s4  = (idx & 3) * 4;
        int row = rowBase + r;
        bool ok = row < M;
        int rowc = ok ? row : 0;
        const uint32_t* src = A + (size_t)rowc * 128 + c * 16 + s4;
        uint32_t dst = sb + (W_A + r * 20 + s4) * 4;
        cp16z(dst, src, ok);
    }
}

__device__ __forceinline__ void cpB(uint32_t sb, const uint32_t* __restrict__ Wq,
                                    int colBase, int c, int tid)
{
    #pragma unroll
    for (int t = 0; t < 2; t++) {
        int idx = tid + t * 256;          // 0..511
        int kp  = idx >> 5;               // 0..15
        int n4  = (idx & 31) * 4;         // 0..124
        const uint32_t* src = Wq + (size_t)(c * 16 + kp) * 256 + colBase + n4;
        uint32_t dst = sb + (W_B + kp * 136 + n4) * 4;
        cp16(dst, src);
    }
}

// ---------------------------------------------------------------------------
// fp16 mma GEMM: 256 threads, 8 warps (4m x 2n), warp 32x64, 4-stage pipeline.
// MODE 0: C fp32 = acc
// MODE 1: CQ fp16-pack = relu(acc+bias) + relu(agg+bagg)
// MODE 2: C fp32 = relu(acc+bias)
// ---------------------------------------------------------------------------
template<int MODE>
__global__ __launch_bounds__(256, 2)
void gemm_mma(const uint32_t* __restrict__ A,
              const uint32_t* __restrict__ Wq,
              const float* __restrict__ bias,
              const float* __restrict__ agg,
              const float* __restrict__ bagg,
              float* __restrict__ C,
              uint32_t* __restrict__ CQ,
              int M)
{
    extern __shared__ uint32_t sm[];
    const int tid  = threadIdx.x;
    const int lane = tid & 31;
    const int wid  = tid >> 5;
    const int wm   = wid & 3;
    const int wn   = wid >> 2;
    const int gid  = lane >> 2;
    const int tig  = lane & 3;
    const int rowBase = blockIdx.x * 128;
    const int colBase = blockIdx.y * 128;

    uint32_t sbase;
    {
        uint64_t a = __cvta_generic_to_shared(sm);
        sbase = (uint32_t)a;
    }

    float acc[2][8][4];
    #pragma unroll
    for (int mt = 0; mt < 2; mt++)
        #pragma unroll
        for (int nt = 0; nt < 8; nt++)
            #pragma unroll
            for (int q = 0; q < 4; q++) acc[mt][nt][q] = 0.f;

    // prologue: stages 0..2
    #pragma unroll
    for (int p = 0; p < 3; p++) {
        uint32_t pb = sbase + p * (WBUF * 4);
        cpA(pb, A, M, rowBase, p, tid);
        cpB(pb, Wq, colBase, p, tid);
        CP_COMMIT();
    }

    #pragma unroll
    for (int c = 0; c < 8; c++) {
        if (c < 5) {
            uint32_t nb = sbase + ((c + 3) & 3) * (WBUF * 4);
            cpA(nb, A, M, rowBase, c + 3, tid);
            cpB(nb, Wq, colBase, c + 3, tid);
            CP_COMMIT();
        }
        // wait for group c to complete (allowed outstanding beyond c)
        if (c < 5)      CP_WAIT(3);
        else if (c == 5) CP_WAIT(2);
        else if (c == 6) CP_WAIT(1);
        else             CP_WAIT(0);
        __syncthreads();

        const uint32_t* buf = sm + (c & 3) * WBUF;
        const uint32_t* sA = buf + W_A;
        const uint32_t* sB = buf + W_B;

        #pragma unroll
        for (int ks = 0; ks < 2; ks++) {
            uint32_t a[2][4];
            #pragma unroll
            for (int mt = 0; mt < 2; mt++) {
                int off = (wm * 32 + mt * 16 + gid) * 20 + ks * 8 + tig;
                a[mt][0] = sA[off];       a[mt][1] = sA[off + 160];
                a[mt][2] = sA[off + 4];   a[mt][3] = sA[off + 164];
            }
            #pragma unroll
            for (int nt = 0; nt < 8; nt++) {
                int bi = (ks * 8 + tig) * 136 + wn * 64 + nt * 8 + gid;
                uint32_t b0 = sB[bi], b1 = sB[bi + 544];
                #pragma unroll
                for (int mt = 0; mt < 2; mt++)
                    mma16816(acc[mt][nt], a[mt], b0, b1);
            }
        }
        __syncthreads();
    }

    // ------------------------------ epilogue -------------------------------
    #pragma unroll
    for (int mt = 0; mt < 2; mt++) {
        #pragma unroll
        for (int nt = 0; nt < 8; nt++) {
            int r0  = rowBase + wm * 32 + mt * 16 + gid;
            int r1  = r0 + 8;
            int col = colBase + wn * 64 + nt * 8 + 2 * tig;
            float* a4 = acc[mt][nt];
            if (MODE == 0) {
                if (r0 < M)
                    *reinterpret_cast<float2*>(C + (size_t)r0 * 256 + col) =
                        make_float2(a4[0], a4[1]);
                if (r1 < M)
                    *reinterpret_cast<float2*>(C + (size_t)r1 * 256 + col) =
                        make_float2(a4[2], a4[3]);
            } else if (MODE == 1) {
                float2 bs = *reinterpret_cast<const float2*>(bias + col);
                float2 ba = *reinterpret_cast<const float2*>(bagg + col);
                if (r0 < M) {
                    float2 ag = *reinterpret_cast<const float2*>(agg + (size_t)r0 * 256 + col);
                    float v0 = frelu(a4[0] + bs.x) + frelu(ag.x + ba.x);
                    float v1 = frelu(a4[1] + bs.y) + frelu(ag.y + ba.y);
                    CQ[(size_t)r0 * 128 + (col >> 1)] = pack_f16(v0, v1);
                }
                if (r1 < M) {
                    float2 ag = *reinterpret_cast<const float2*>(agg + (size_t)r1 * 256 + col);
                    float v0 = frelu(a4[2] + bs.x) + frelu(ag.x + ba.x);
                    float v1 = frelu(a4[3] + bs.y) + frelu(ag.y + ba.y);
                    CQ[(size_t)r1 * 128 + (col >> 1)] = pack_f16(v0, v1);
                }
            } else {
                float2 bs = *reinterpret_cast<const float2*>(bias + col);
                if (r0 < M)
                    *reinterpret_cast<float2*>(C + (size_t)r0 * 256 + col) =
                        make_float2(frelu(a4[0] + bs.x), frelu(a4[1] + bs.y));
                if (r1 < M)
                    *reinterpret_cast<float2*>(C + (size_t)r1 * 256 + col) =
                        make_float2(frelu(a4[2] + bs.x), frelu(a4[3] + bs.y));
            }
        }
    }
}

// ---------------------------------------------------------------------------
// Conversion kernels (fp32 -> packed fp16)
// ---------------------------------------------------------------------------
__global__ __launch_bounds__(256)
void conv_nf(const float* __restrict__ n1, const float* __restrict__ n2,
             uint32_t* __restrict__ Q)
{
    size_t idx = (size_t)blockIdx.x * blockDim.x + threadIdx.x;
    if (idx >= 2 * (size_t)NW) return;
    int br = idx >= (size_t)NW;
    size_t w = idx - (size_t)br * NW;
    const float* nf = br ? n2 : n1;
    float2 v = *reinterpret_cast<const float2*>(nf + w * 2);
    Q[idx] = pack_f16(v.x, v.y);
}

__global__ __launch_bounds__(256)
void conv_W(const float* __restrict__ m0, const float* __restrict__ m1,
            const float* __restrict__ m2, const float* __restrict__ m3,
            const float* __restrict__ m4, const float* __restrict__ m5,
            uint32_t* __restrict__ WQ)
{
    int idx = blockIdx.x * blockDim.x + threadIdx.x;
    if (idx >= 6 * 128 * 256) return;
    int m    = idx >> 15;
    int rest = idx & 32767;
    int k2   = rest >> 8;
    int n    = rest & 255;
    const float* Wm = (m == 0) ? m0 : (m == 1) ? m1 : (m == 2) ? m2
                    : (m == 3) ? m3 : (m == 4) ? m4 : m5;
    float a = Wm[(size_t)(2 * k2) * 256 + n];
    float b = Wm[(size_t)(2 * k2 + 1) * 256 + n];
    WQ[idx] = pack_f16(a, b);
}

// ---------------------------------------------------------------------------
// CSR build, both branches (on s2)
// ---------------------------------------------------------------------------
__global__ void hist_kernel(const int* __restrict__ dst1, const int* __restrict__ dst2,
                            int* __restrict__ deg)
{
    int idx = blockIdx.x * blockDim.x + threadIdx.x;
    if (idx < 2 * N_EDGES) {
        int br = idx >= N_EDGES;
        int e  = idx - br * N_EDGES;
        int d  = br ? dst2[e] : dst1[e];
        atomicAdd(&deg[br * N_NODES + d], 1);
    }
}

__global__ __launch_bounds__(256)
void scan1_kernel(const int* __restrict__ degAll, int* __restrict__ rowstartAll,
                  int* __restrict__ bsums)
{
    __shared__ int wsum[8];
    int br  = blockIdx.x / SCAN_BLKS;
    int blk = blockIdx.x % SCAN_BLKS;
    int t = threadIdx.x, lane = t & 31, w = t >> 5;
    const int* deg = degAll + br * N_NODES;
    int* rowstart  = rowstartAll + br * (N_NODES + 1);

    int base = blk * SCAN_CHUNK + t * 4;
    int v[4];
    #pragma unroll
    for (int i = 0; i < 4; i++)
        v[i] = (base + i < N_NODES) ? deg[base + i] : 0;
    int s = v[0] + v[1] + v[2] + v[3];

    int x = s;
    #pragma unroll
    for (int o = 1; o < 32; o <<= 1) {
        int n = __shfl_up_sync(0xFFFFFFFFu, x, o);
        if (lane >= o) x += n;
    }
    if (lane == 31) wsum[w] = x;
    __syncthreads();
    if (w == 0 && lane < 8) {
        int y = wsum[lane];
        #pragma unroll
        for (int o = 1; o < 8; o <<= 1) {
            int n = __shfl_up_sync(0xFFu, y, o);
            if (lane >= o) y += n;
        }
        wsum[lane] = y;
    }
    __syncthreads();
    int excl = x - s + (w > 0 ? wsum[w - 1] : 0);

    int run = excl;
    #pragma unroll
    for (int i = 0; i < 4; i++) {
        if (base + i < N_NODES) rowstart[base + i] = run;
        run += v[i];
    }
    if (t == 255) bsums[br * SCAN_BLKS + blk] = wsum[7];
}

__global__ __launch_bounds__(256)
void scan2_kernel(const int* __restrict__ bsums, int* __restrict__ rowstartAll,
                  int* __restrict__ cursorAll)
{
    __shared__ int soff;
    int br  = blockIdx.x / SCAN_BLKS;
    int blk = blockIdx.x % SCAN_BLKS;
    int t = threadIdx.x;
    int* rowstart = rowstartAll + br * (N_NODES + 1);
    int* cursor   = cursorAll   + br * N_NODES;

    if (t == 0) {
        int off = 0;
        for (int j = 0; j < blk; j++) off += bsums[br * SCAN_BLKS + j];
        soff = off;
        if (blockIdx.x == 0) {
            rowstartAll[N_NODES] = N_EDGES;
            rowstartAll[(N_NODES + 1) + N_NODES] = N_EDGES;
        }
    }
    __syncthreads();
    int off = soff;
    int base = blk * SCAN_CHUNK + t * 4;
    #pragma unroll
    for (int i = 0; i < 4; i++) {
        int g = base + i;
        if (g < N_NODES) {
            int val = rowstart[g] + off;
            rowstart[g] = val;
            cursor[g]   = val;
        }
    }
}

__global__ void fill_kernel(const int* __restrict__ src1, const int* __restrict__ dst1,
                            const int* __restrict__ src2, const int* __restrict__ dst2,
                            int* __restrict__ cursorAll, int* __restrict__ csrAll)
{
    int idx = blockIdx.x * blockDim.x + threadIdx.x;
    if (idx < 2 * N_EDGES) {
        int br = idx >= N_EDGES;
        int e  = idx - br * N_EDGES;
        int d  = br ? dst2[e] : dst1[e];
        int s  = br ? src2[e] : src1[e];
        int p  = atomicAdd(&cursorAll[br * N_NODES + d], 1);
        csrAll[br * N_EDGES + p] = s;
    }
}

// ---------------------------------------------------------------------------
// Warp-per-node gather of fp16-packed features: one uint4 per lane per row.
// fp32 accumulation, fp16-packed output.
// ---------------------------------------------------------------------------
__global__ __launch_bounds__(256)
void gather_f16(const uint32_t* __restrict__ nfQ,
                const int* __restrict__ rowstart,
                const int* __restrict__ csr,
                uint32_t* __restrict__ aggQ)
{
    int node = (blockIdx.x * blockDim.x + threadIdx.x) >> 5;
    int lane = threadIdx.x & 31;
    if (node >= N_NODES) return;

    int beg = rowstart[node], end = rowstart[node + 1];
    float a[8];
    #pragma unroll
    for (int i = 0; i < 8; i++) a[i] = 0.f;
    float b[8];
    #pragma unroll
    for (int i = 0; i < 8; i++) b[i] = 0.f;

    int e = beg;
    for (; e + 1 < end; e += 2) {
        uint4 u = reinterpret_cast<const uint4*>(nfQ + (size_t)csr[e]     * 128)[lane];
        uint4 v = reinterpret_cast<const uint4*>(nfQ + (size_t)csr[e + 1] * 128)[lane];
        float2 f;
        f = __half22float2(*reinterpret_cast<__half2*>(&u.x)); a[0] += f.x; a[1] += f.y;
        f = __half22float2(*reinterpret_cast<__half2*>(&u.y)); a[2] += f.x; a[3] += f.y;
        f = __half22float2(*reinterpret_cast<__half2*>(&u.z)); a[4] += f.x; a[5] += f.y;
        f = __half22float2(*reinterpret_cast<__half2*>(&u.w)); a[6] += f.x; a[7] += f.y;
        f = __half22float2(*reinterpret_cast<__half2*>(&v.x)); b[0] += f.x; b[1] += f.y;
        f = __half22float2(*reinterpret_cast<__half2*>(&v.y)); b[2] += f.x; b[3] += f.y;
        f = __half22float2(*reinterpret_cast<__half2*>(&v.z)); b[4] += f.x; b[5] += f.y;
        f = __half22float2(*reinterpret_cast<__half2*>(&v.w)); b[6] += f.x; b[7] += f.y;
    }
    if (e < end) {
        uint4 u = reinterpret_cast<const uint4*>(nfQ + (size_t)csr[e] * 128)[lane];
        float2 f;
        f = __half22float2(*reinterpret_cast<__half2*>(&u.x)); a[0] += f.x; a[1] += f.y;
        f = __half22float2(*reinterpret_cast<__half2*>(&u.y)); a[2] += f.x; a[3] += f.y;
        f = __half22float2(*reinterpret_cast<__half2*>(&u.z)); a[4] += f.x; a[5] += f.y;
        f = __half22float2(*reinterpret_cast<__half2*>(&u.w)); a[6] += f.x; a[7] += f.y;
    }
    #pragma unroll
    for (int i = 0; i < 8; i++) a[i] += b[i];

    uint4 o;
    o.x = pack_f16(a[0], a[1]);
    o.y = pack_f16(a[2], a[3]);
    o.z = pack_f16(a[4], a[5]);
    o.w = pack_f16(a[6], a[7]);
    reinterpret_cast<uint4*>(aggQ + (size_t)node * 128)[lane] = o;
}

// ---------------------------------------------------------------------------
// Segment sum (sorted gid), single branch
// ---------------------------------------------------------------------------
__global__ __launch_bounds__(256)
void segsum_kernel(const float* __restrict__ h2, const int* __restrict__ gid,
                   float* __restrict__ T, int* __restrict__ counts)
{
    __shared__ int sb, se;
    int g = blockIdx.x;
    if (threadIdx.x == 0) {
        int lo = 0, hi = N_NODES;
        while (lo < hi) { int m = (lo + hi) >> 1; if (gid[m] < g) lo = m + 1; else hi = m; }
        sb = lo;
        lo = sb; hi = N_NODES;
        while (lo < hi) { int m = (lo + hi) >> 1; if (gid[m] < g + 1) lo = m + 1; else hi = m; }
        se = lo;
        counts[g] = se - sb;
    }
    __syncthreads();
    int beg = sb, end = se, c = threadIdx.x;
    float s = 0.f;
    for (int r = beg; r < end; r++)
        s += h2[(size_t)r * DFEAT + c];
    T[(size_t)g * DFEAT + c] = s;
}

// ---------------------------------------------------------------------------
// Fused readout + predictor
// ---------------------------------------------------------------------------
__global__ __launch_bounds__(256)
void readout_final(const float* __restrict__ TAll, const int* __restrict__ countsAll,
                   const float* __restrict__ Ro1, const float* __restrict__ rbo1,
                   const float* __restrict__ Ro2, const float* __restrict__ rbo2,
                   const float* __restrict__ Wp, const float* __restrict__ bp,
                   float* __restrict__ out)
{
    __shared__ float ts1[DFEAT], ts2[DFEAT];
    __shared__ float red[256];
    int g = blockIdx.x;
    int t = threadIdx.x;
    ts1[t] = TAll[(size_t)g * DFEAT + t];
    ts2[t] = TAll[((size_t)N_GRAPHS + g) * DFEAT + t];
    __syncthreads();
    float c1 = (float)countsAll[g];
    float c2 = (float)countsAll[N_GRAPHS + g];
    float partial = 0.f;
    if (t < G_FEAT) {
        float s = c1 * rbo1[t] + c2 * rbo2[t];
        #pragma unroll 8
        for (int k = 0; k < DFEAT; k++)
            s += ts1[k] * Ro1[(size_t)k * G_FEAT + t]
               + ts2[k] * Ro2[(size_t)k * G_FEAT + t];
        partial = s * Wp[t];
    }
    red[t] = partial;
    __syncthreads();
    #pragma unroll
    for (int st = 128; st > 0; st >>= 1) {
        if (t < st) red[t] += red[t + st];
        __syncthreads();
    }
    if (t == 0) out[g] = red[0] + bp[0];
}

// ---------------------------------------------------------------------------
extern "C" void kernel_launch(void* const* d_in, const int* in_sizes, int n_in,
                              void* d_out, int out_size)
{
    const float* nf1 = (const float*)d_in[0];
    const float* nf2 = (const float*)d_in[2];
    const int* src1 = (const int*)d_in[4];
    const int* dst1 = (const int*)d_in[5];
    const int* gid1 = (const int*)d_in[6];
    const int* src2 = (const int*)d_in[7];
    const int* dst2 = (const int*)d_in[8];
    const int* gid2 = (const int*)d_in[9];
    const float* W1  = (const float*)d_in[10]; const float* b1  = (const float*)d_in[11];
    const float* Wr1 = (const float*)d_in[12]; const float* br1 = (const float*)d_in[13];
    const float* W2  = (const float*)d_in[14]; const float* b2  = (const float*)d_in[15];
    const float* Wr2 = (const float*)d_in[16]; const float* br2 = (const float*)d_in[17];
    const float* Ri1 = (const float*)d_in[18]; const float* rbi1 = (const float*)d_in[19];
    const float* Ro1 = (const float*)d_in[20]; const float* rbo1 = (const float*)d_in[21];
    const float* Ri2 = (const float*)d_in[22]; const float* rbi2 = (const float*)d_in[23];
    const float* Ro2 = (const float*)d_in[24]; const float* rbo2 = (const float*)d_in[25];
    const float* Wp  = (const float*)d_in[26]; const float* bp   = (const float*)d_in[27];

    float *t2, *T;
    uint32_t *aggQ, *nfQ, *h1Q, *WQ;
    int *counts, *deg, *rowstart, *cursor, *csr_src, *bsums;
    cudaGetSymbolAddress((void**)&t2,       g_t2);
    cudaGetSymbolAddress((void**)&aggQ,     g_aggQ);
    cudaGetSymbolAddress((void**)&nfQ,      g_nfQ);
    cudaGetSymbolAddress((void**)&h1Q,      g_h1Q);
    cudaGetSymbolAddress((void**)&WQ,       g_WQ);
    cudaGetSymbolAddress((void**)&T,        g_T);
    cudaGetSymbolAddress((void**)&counts,   g_counts);
    cudaGetSymbolAddress((void**)&deg,      g_deg);
    cudaGetSymbolAddress((void**)&rowstart, g_rowstart);
    cudaGetSymbolAddress((void**)&cursor,   g_cursor);
    cudaGetSymbolAddress((void**)&csr_src,  g_csr_src);
    cudaGetSymbolAddress((void**)&bsums,    g_bsums);

    cudaFuncSetAttribute(gemm_mma<0>, cudaFuncAttributeMaxDynamicSharedMemorySize, SMEM_BYTES);
    cudaFuncSetAttribute(gemm_mma<1>, cudaFuncAttributeMaxDynamicSharedMemorySize, SMEM_BYTES);
    cudaFuncSetAttribute(gemm_mma<2>, cudaFuncAttributeMaxDynamicSharedMemorySize, SMEM_BYTES);

    // Lazy streams + events (created on the first, uncaptured, call).
    static cudaStream_t s_s2 = nullptr, s_s3 = nullptr;
    static cudaEvent_t  s_evF = nullptr, s_evNF = nullptr, s_evConv = nullptr,
                        s_evG1 = nullptr, s_evG2 = nullptr, s_evJ3 = nullptr;
    static bool s_tried = false;
    if (!s_tried) {
        s_tried = true;
        bool ok =
            cudaStreamCreateWithFlags(&s_s2, cudaStreamNonBlocking) == cudaSuccess &&
            cudaStreamCreateWithFlags(&s_s3, cudaStreamNonBlocking) == cudaSuccess &&
            cudaEventCreateWithFlags(&s_evF,    cudaEventDisableTiming) == cudaSuccess &&
            cudaEventCreateWithFlags(&s_evNF,   cudaEventDisableTiming) == cudaSuccess &&
            cudaEventCreateWithFlags(&s_evConv, cudaEventDisableTiming) == cudaSuccess &&
            cudaEventCreateWithFlags(&s_evG1,   cudaEventDisableTiming) == cudaSuccess &&
            cudaEventCreateWithFlags(&s_evG2,   cudaEventDisableTiming) == cudaSuccess &&
            cudaEventCreateWithFlags(&s_evJ3,   cudaEventDisableTiming) == cudaSuccess;
        if (!ok) { s_s2 = nullptr; s_s3 = nullptr; }
    }
    const bool par = (s_s2 != nullptr);
    cudaStream_t s0 = (cudaStream_t)0;
    cudaStream_t s2 = par ? s_s2 : s0;
    cudaStream_t s3 = par ? s_s3 : s0;

    float* t2_1 = t2;   float* t2_2 = t2 + (size_t)N_NODES * DFEAT;
    float* T1   = T;    float* T2   = T  + (size_t)N_GRAPHS * DFEAT;
    int* counts1 = counts;  int* counts2 = counts + N_GRAPHS;
    uint32_t* aggQ1 = aggQ; uint32_t* aggQ2 = aggQ + (size_t)NW;
    uint32_t* nfQ1 = nfQ;   uint32_t* nfQ2 = nfQ + (size_t)NW;
    uint32_t* h1Q1 = h1Q;   uint32_t* h1Q2 = h1Q + (size_t)NW;
    const int* rs1 = rowstart;              const int* rs2 = rowstart + (N_NODES + 1);
    const int* cs1 = csr_src;               const int* cs2 = csr_src + N_EDGES;
    const int WSZ = 128 * 256;   // slots: 0=W1 1=Wr1 2=Ri1 3=W2 4=Wr2 5=Ri2

    dim3 gemm_grid((N_NODES + 127) / 128, 2);       // per-branch: 391 x 2
    int eb2 = (2 * N_EDGES + 255) / 256;
    int gat_blocks = (N_NODES * 32 + 255) / 256;

    // ---- fork ----
    if (par) {
        cudaEventRecord(s_evF, s0);
        cudaStreamWaitEvent(s_s2, s_evF, 0);
        cudaStreamWaitEvent(s_s3, s_evF, 0);
    }

    // s0: conversions first (gathers depend on conv_nf)
    conv_nf<<<(int)((2 * (size_t)NW + 255) / 256), 256, 0, s0>>>(nf1, nf2, nfQ);
    if (par) cudaEventRecord(s_evNF, s0);
    conv_W<<<(6 * 128 * 256 + 255) / 256, 256, 0, s0>>>(W1, Wr1, Ri1, W2, Wr2, Ri2, WQ);
    if (par) cudaEventRecord(s_evConv, s0);

    // s2: CSR chain, then both fp16 gathers (wait conv_nf)
    cudaMemsetAsync(deg, 0, 2 * N_NODES * sizeof(int), s2);
    hist_kernel<<<eb2, 256, 0, s2>>>(dst1, dst2, deg);
    scan1_kernel<<<2 * SCAN_BLKS, 256, 0, s2>>>(deg, rowstart, bsums);
    scan2_kernel<<<2 * SCAN_BLKS, 256, 0, s2>>>(bsums, rowstart, cursor);
    fill_kernel<<<eb2, 256, 0, s2>>>(src1, dst1, src2, dst2, cursor, csr_src);
    if (par) cudaStreamWaitEvent(s_s2, s_evNF, 0);
    gather_f16<<<gat_blocks, 256, 0, s2>>>(nfQ1, rs1, cs1, aggQ1);
    if (par) cudaEventRecord(s_evG1, s_s2);
    gather_f16<<<gat_blocks, 256, 0, s2>>>(nfQ2, rs2, cs2, aggQ2);
    if (par) cudaEventRecord(s_evG2, s_s2);

    // s0: branch-1 GEMM chain
    gemm_mma<0><<<gemm_grid, 256, SMEM_BYTES, s0>>>(
        nfQ1, WQ + 1 * WSZ, nullptr, nullptr, nullptr, t2_1, nullptr, N_NODES);
    if (par) cudaStreamWaitEvent(s0, s_evG1, 0);
    gemm_mma<1><<<gemm_grid, 256, SMEM_BYTES, s0>>>(
        aggQ1, WQ + 0 * WSZ, b1, t2_1, br1, nullptr, h1Q1, N_NODES);
    gemm_mma<2><<<gemm_grid, 256, SMEM_BYTES, s0>>>(
        h1Q1, WQ + 2 * WSZ, rbi1, nullptr, nullptr, t2_1, nullptr, N_NODES);
    segsum_kernel<<<N_GRAPHS, 256, 0, s0>>>(t2_1, gid1, T1, counts1);

    // s3: branch-2 GEMM chain
    if (par) cudaStreamWaitEvent(s_s3, s_evConv, 0);
    gemm_mma<0><<<gemm_grid, 256, SMEM_BYTES, s3>>>(
        nfQ2, WQ + 4 * WSZ, nullptr, nullptr, nullptr, t2_2, nullptr, N_NODES);
    if (par) cudaStreamWaitEvent(s_s3, s_evG2, 0);
    gemm_mma<1><<<gemm_grid, 256, SMEM_BYTES, s3>>>(
        aggQ2, WQ + 3 * WSZ, b2, t2_2, br2, nullptr, h1Q2, N_NODES);
    gemm_mma<2><<<gemm_grid, 256, SMEM_BYTES, s3>>>(
        h1Q2, WQ + 5 * WSZ, rbi2, nullptr, nullptr, t2_2, nullptr, N_NODES);
    segsum_kernel<<<N_GRAPHS, 256, 0, s3>>>(t2_2, gid2, T2, counts2);
    if (par) cudaEventRecord(s_evJ3, s_s3);

    // join + fused readout/predictor
    if (par) cudaStreamWaitEvent(s0, s_evJ3, 0);
    readout_final<<<N_GRAPHS, 256, 0, s0>>>(T, counts, Ro1, rbo1, Ro2, rbo2, Wp, bp,
                                            (float*)d_out);
}

// round 15
// speedup vs baseline: 1.6424x; 1.0728x over previous
#include <cuda_runtime.h>
#include <cuda_fp16.h>
#include <cstdint>
#include <cstddef>

// ---------------------------------------------------------------------------
// mulGCN: two-branch GCN forward, fp16 mma.sync GEMMs + 4-stage cp.async
// pipeline. R15: ALL node-sized intermediates are packed fp16 (t2 and h2
// included), halving the GEMM-epilogue and segsum memory traffic.
// Schedule:
//   s0: conv_nf (evNF) -> conv_W (evConv) -> branch-1 GEMM chain
//   s2: CSR chain -> [wait evNF] gather1 (evG1) -> gather2 (evG2)
//   s3: [wait evConv] branch-2 GEMM chain
//   t2 = h@Wr (fp16); h1 = relu(hagg@W+b)+relu(t2+br) (fp16);
//   h2 = relu(h1@Ri+rbi) (fp16); T[g] = segsum h2 (fp32);
//   out = (T1@Ro1 + c1*rbo1 + T2@Ro2 + c2*rbo2) . Wp + bp
// ---------------------------------------------------------------------------

#define N_NODES   50000
#define N_EDGES   800000
#define DFEAT     256
#define G_FEAT    200
#define N_GRAPHS  512

#define NW   (N_NODES * 128)          // fp16-pair words per branch

#define SCAN_BLKS   49
#define SCAN_CHUNK  1024

__device__ uint32_t g_t2Q [2][(size_t)NW];   // h@Wr fp16; reused as h2
__device__ uint32_t g_aggQ[2][(size_t)NW];
__device__ uint32_t g_nfQ [2][(size_t)NW];
__device__ uint32_t g_h1Q [2][(size_t)NW];
__device__ uint32_t g_WQ  [6][128 * 256];   // k-major pairs: [kp][n]
__device__ float    g_T   [2][N_GRAPHS * DFEAT];
__device__ int      g_counts  [2][N_GRAPHS];
__device__ int      g_deg     [2][N_NODES];
__device__ int      g_rowstart[2][N_NODES + 1];
__device__ int      g_cursor  [2][N_NODES];
__device__ int      g_csr_src [2][N_EDGES];
__device__ int      g_bsums   [2 * SCAN_BLKS];

__device__ __forceinline__ float frelu(float x) { return x > 0.f ? x : 0.f; }

// ------------------------- mma / pack helpers ------------------------------
__device__ __forceinline__ void mma16816(float* c, const uint32_t* a,
                                         uint32_t b0, uint32_t b1) {
    asm volatile(
        "mma.sync.aligned.m16n8k16.row.col.f32.f16.f16.f32 "
        "{%0,%1,%2,%3}, {%4,%5,%6,%7}, {%8,%9}, {%0,%1,%2,%3};\n"
        : "+f"(c[0]), "+f"(c[1]), "+f"(c[2]), "+f"(c[3])
        : "r"(a[0]), "r"(a[1]), "r"(a[2]), "r"(a[3]), "r"(b0), "r"(b1));
}

__device__ __forceinline__ uint32_t pack_f16(float x, float y) {
    __half2 t;
    t.x = __float2half_rn(x);
    t.y = __float2half_rn(y);
    return *reinterpret_cast<uint32_t*>(&t);
}
__device__ __forceinline__ float2 unpack_f16(uint32_t w) {
    return __half22float2(*reinterpret_cast<__half2*>(&w));
}

// ------------------------- cp.async helpers --------------------------------
__device__ __forceinline__ void cp16(uint32_t dst, const void* src) {
    asm volatile("cp.async.cg.shared.global [%0], [%1], 16;"
                 :: "r"(dst), "l"(src));
}
__device__ __forceinline__ void cp16z(uint32_t dst, const void* src, bool ok) {
    int b = ok ? 16 : 0;
    asm volatile("cp.async.cg.shared.global [%0], [%1], 16, %2;"
                 :: "r"(dst), "l"(src), "r"(b));
}
#define CP_COMMIT()  asm volatile("cp.async.commit_group;" ::: "memory")
#define CP_WAIT(n)   asm volatile("cp.async.wait_group %0;" :: "n"(n) : "memory")

// SMEM words per buffer: A[128][20]  B[16][136]; 4 buffers
static constexpr int W_A = 0, W_B = 2560;
static constexpr int WBUF = 4736;
static constexpr int N_STAGE = 4;
static constexpr int SMEM_BYTES = N_STAGE * WBUF * 4;   // 75776

__device__ __forceinline__ void cpA(uint32_t sb, const uint32_t* __restrict__ A,
                                    int M, int rowBase, int c, int tid)
{
    #pragma unroll
    for (int t = 0; t < 2; t++) {
        int idx = tid + t * 256;          // 0..511
        int r   = idx >> 2;
        int s4  = (idx & 3) * 4;
        int row = rowBase + r;
        bool ok = row < M;
        int rowc = ok ? row : 0;
        const uint32_t* src = A + (size_t)rowc * 128 + c * 16 + s4;
        uint32_t dst = sb + (W_A + r * 20 + s4) * 4;
        cp16z(dst, src, ok);
    }
}

__device__ __forceinline__ void cpB(uint32_t sb, const uint32_t* __restrict__ Wq,
                                    int colBase, int c, int tid)
{
    #pragma unroll
    for (int t = 0; t < 2; t++) {
        int idx = tid + t * 256;          // 0..511
        int kp  = idx >> 5;               // 0..15
        int n4  = (idx & 31) * 4;         // 0..124
        const uint32_t* src = Wq + (size_t)(c * 16 + kp) * 256 + colBase + n4;
        uint32_t dst = sb + (W_B + kp * 136 + n4) * 4;
        cp16(dst, src);
    }
}

// ---------------------------------------------------------------------------
// fp16 mma GEMM: 256 threads, 8 warps (4m x 2n), warp 32x64, 4-stage pipeline.
// All outputs packed fp16.
// MODE 0: CQ = pack(acc)
// MODE 1: CQ = pack(relu(acc+bias) + relu(unpack(aggQ)+bagg))
// MODE 2: CQ = pack(relu(acc+bias))
// ---------------------------------------------------------------------------
template<int MODE>
__global__ __launch_bounds__(256, 2)
void gemm_mma(const uint32_t* __restrict__ A,
              const uint32_t* __restrict__ Wq,
              const float* __restrict__ bias,
              const uint32_t* __restrict__ aggQ,
              const float* __restrict__ bagg,
              uint32_t* __restrict__ CQ,
              int M)
{
    extern __shared__ uint32_t sm[];
    const int tid  = threadIdx.x;
    const int lane = tid & 31;
    const int wid  = tid >> 5;
    const int wm   = wid & 3;
    const int wn   = wid >> 2;
    const int gid  = lane >> 2;
    const int tig  = lane & 3;
    const int rowBase = blockIdx.x * 128;
    const int colBase = blockIdx.y * 128;

    uint32_t sbase;
    {
        uint64_t a = __cvta_generic_to_shared(sm);
        sbase = (uint32_t)a;
    }

    float acc[2][8][4];
    #pragma unroll
    for (int mt = 0; mt < 2; mt++)
        #pragma unroll
        for (int nt = 0; nt < 8; nt++)
            #pragma unroll
            for (int q = 0; q < 4; q++) acc[mt][nt][q] = 0.f;

    #pragma unroll
    for (int p = 0; p < 3; p++) {
        uint32_t pb = sbase + p * (WBUF * 4);
        cpA(pb, A, M, rowBase, p, tid);
        cpB(pb, Wq, colBase, p, tid);
        CP_COMMIT();
    }

    #pragma unroll
    for (int c = 0; c < 8; c++) {
        if (c < 5) {
            uint32_t nb = sbase + ((c + 3) & 3) * (WBUF * 4);
            cpA(nb, A, M, rowBase, c + 3, tid);
            cpB(nb, Wq, colBase, c + 3, tid);
            CP_COMMIT();
        }
        if (c < 5)       CP_WAIT(3);
        else if (c == 5) CP_WAIT(2);
        else if (c == 6) CP_WAIT(1);
        else             CP_WAIT(0);
        __syncthreads();

        const uint32_t* buf = sm + (c & 3) * WBUF;
        const uint32_t* sA = buf + W_A;
        const uint32_t* sB = buf + W_B;

        #pragma unroll
        for (int ks = 0; ks < 2; ks++) {
            uint32_t a[2][4];
            #pragma unroll
            for (int mt = 0; mt < 2; mt++) {
                int off = (wm * 32 + mt * 16 + gid) * 20 + ks * 8 + tig;
                a[mt][0] = sA[off];       a[mt][1] = sA[off + 160];
                a[mt][2] = sA[off + 4];   a[mt][3] = sA[off + 164];
            }
            #pragma unroll
            for (int nt = 0; nt < 8; nt++) {
                int bi = (ks * 8 + tig) * 136 + wn * 64 + nt * 8 + gid;
                uint32_t b0 = sB[bi], b1 = sB[bi + 544];
                #pragma unroll
                for (int mt = 0; mt < 2; mt++)
                    mma16816(acc[mt][nt], a[mt], b0, b1);
            }
        }
        __syncthreads();
    }

    // ------------------------------ epilogue -------------------------------
    #pragma unroll
    for (int mt = 0; mt < 2; mt++) {
        #pragma unroll
        for (int nt = 0; nt < 8; nt++) {
            int r0  = rowBase + wm * 32 + mt * 16 + gid;
            int r1  = r0 + 8;
            int col = colBase + wn * 64 + nt * 8 + 2 * tig;
            int wc  = col >> 1;
            float* a4 = acc[mt][nt];
            if (MODE == 0) {
                if (r0 < M) CQ[(size_t)r0 * 128 + wc] = pack_f16(a4[0], a4[1]);
                if (r1 < M) CQ[(size_t)r1 * 128 + wc] = pack_f16(a4[2], a4[3]);
            } else if (MODE == 1) {
                float2 bs = *reinterpret_cast<const float2*>(bias + col);
                float2 ba = *reinterpret_cast<const float2*>(bagg + col);
                if (r0 < M) {
                    float2 ag = unpack_f16(aggQ[(size_t)r0 * 128 + wc]);
                    CQ[(size_t)r0 * 128 + wc] = pack_f16(
                        frelu(a4[0] + bs.x) + frelu(ag.x + ba.x),
                        frelu(a4[1] + bs.y) + frelu(ag.y + ba.y));
                }
                if (r1 < M) {
                    float2 ag = unpack_f16(aggQ[(size_t)r1 * 128 + wc]);
                    CQ[(size_t)r1 * 128 + wc] = pack_f16(
                        frelu(a4[2] + bs.x) + frelu(ag.x + ba.x),
                        frelu(a4[3] + bs.y) + frelu(ag.y + ba.y));
                }
            } else {
                float2 bs = *reinterpret_cast<const float2*>(bias + col);
                if (r0 < M)
                    CQ[(size_t)r0 * 128 + wc] = pack_f16(frelu(a4[0] + bs.x),
                                                         frelu(a4[1] + bs.y));
                if (r1 < M)
                    CQ[(size_t)r1 * 128 + wc] = pack_f16(frelu(a4[2] + bs.x),
                                                         frelu(a4[3] + bs.y));
            }
        }
    }
}

// ---------------------------------------------------------------------------
// Conversion kernels (fp32 -> packed fp16)
// ---------------------------------------------------------------------------
__global__ __launch_bounds__(256)
void conv_nf(const float* __restrict__ n1, const float* __restrict__ n2,
             uint32_t* __restrict__ Q)
{
    size_t idx = (size_t)blockIdx.x * blockDim.x + threadIdx.x;
    if (idx >= 2 * (size_t)NW) return;
    int br = idx >= (size_t)NW;
    size_t w = idx - (size_t)br * NW;
    const float* nf = br ? n2 : n1;
    float2 v = *reinterpret_cast<const float2*>(nf + w * 2);
    Q[idx] = pack_f16(v.x, v.y);
}

__global__ __launch_bounds__(256)
void conv_W(const float* __restrict__ m0, const float* __restrict__ m1,
            const float* __restrict__ m2, const float* __restrict__ m3,
            const float* __restrict__ m4, const float* __restrict__ m5,
            uint32_t* __restrict__ WQ)
{
    int idx = blockIdx.x * blockDim.x + threadIdx.x;
    if (idx >= 6 * 128 * 256) return;
    int m    = idx >> 15;
    int rest = idx & 32767;
    int k2   = rest >> 8;
    int n    = rest & 255;
    const float* Wm = (m == 0) ? m0 : (m == 1) ? m1 : (m == 2) ? m2
                    : (m == 3) ? m3 : (m == 4) ? m4 : m5;
    float a = Wm[(size_t)(2 * k2) * 256 + n];
    float b = Wm[(size_t)(2 * k2 + 1) * 256 + n];
    WQ[idx] = pack_f16(a, b);
}

// ---------------------------------------------------------------------------
// CSR build, both branches (on s2)
// ---------------------------------------------------------------------------
__global__ void hist_kernel(const int* __restrict__ dst1, const int* __restrict__ dst2,
                            int* __restrict__ deg)
{
    int idx = blockIdx.x * blockDim.x + threadIdx.x;
    if (idx < 2 * N_EDGES) {
        int br = idx >= N_EDGES;
        int e  = idx - br * N_EDGES;
        int d  = br ? dst2[e] : dst1[e];
        atomicAdd(&deg[br * N_NODES + d], 1);
    }
}

__global__ __launch_bounds__(256)
void scan1_kernel(const int* __restrict__ degAll, int* __restrict__ rowstartAll,
                  int* __restrict__ bsums)
{
    __shared__ int wsum[8];
    int br  = blockIdx.x / SCAN_BLKS;
    int blk = blockIdx.x % SCAN_BLKS;
    int t = threadIdx.x, lane = t & 31, w = t >> 5;
    const int* deg = degAll + br * N_NODES;
    int* rowstart  = rowstartAll + br * (N_NODES + 1);

    int base = blk * SCAN_CHUNK + t * 4;
    int v[4];
    #pragma unroll
    for (int i = 0; i < 4; i++)
        v[i] = (base + i < N_NODES) ? deg[base + i] : 0;
    int s = v[0] + v[1] + v[2] + v[3];

    int x = s;
    #pragma unroll
    for (int o = 1; o < 32; o <<= 1) {
        int n = __shfl_up_sync(0xFFFFFFFFu, x, o);
        if (lane >= o) x += n;
    }
    if (lane == 31) wsum[w] = x;
    __syncthreads();
    if (w == 0 && lane < 8) {
        int y = wsum[lane];
        #pragma unroll
        for (int o = 1; o < 8; o <<= 1) {
            int n = __shfl_up_sync(0xFFu, y, o);
            if (lane >= o) y += n;
        }
        wsum[lane] = y;
    }
    __syncthreads();
    int excl = x - s + (w > 0 ? wsum[w - 1] : 0);

    int run = excl;
    #pragma unroll
    for (int i = 0; i < 4; i++) {
        if (base + i < N_NODES) rowstart[base + i] = run;
        run += v[i];
    }
    if (t == 255) bsums[br * SCAN_BLKS + blk] = wsum[7];
}

__global__ __launch_bounds__(256)
void scan2_kernel(const int* __restrict__ bsums, int* __restrict__ rowstartAll,
                  int* __restrict__ cursorAll)
{
    __shared__ int soff;
    int br  = blockIdx.x / SCAN_BLKS;
    int blk = blockIdx.x % SCAN_BLKS;
    int t = threadIdx.x;
    int* rowstart = rowstartAll + br * (N_NODES + 1);
    int* cursor   = cursorAll   + br * N_NODES;

    if (t == 0) {
        int off = 0;
        for (int j = 0; j < blk; j++) off += bsums[br * SCAN_BLKS + j];
        soff = off;
        if (blockIdx.x == 0) {
            rowstartAll[N_NODES] = N_EDGES;
            rowstartAll[(N_NODES + 1) + N_NODES] = N_EDGES;
        }
    }
    __syncthreads();
    int off = soff;
    int base = blk * SCAN_CHUNK + t * 4;
    #pragma unroll
    for (int i = 0; i < 4; i++) {
        int g = base + i;
        if (g < N_NODES) {
            int val = rowstart[g] + off;
            rowstart[g] = val;
            cursor[g]   = val;
        }
    }
}

__global__ void fill_kernel(const int* __restrict__ src1, const int* __restrict__ dst1,
                            const int* __restrict__ src2, const int* __restrict__ dst2,
                            int* __restrict__ cursorAll, int* __restrict__ csrAll)
{
    int idx = blockIdx.x * blockDim.x + threadIdx.x;
    if (idx < 2 * N_EDGES) {
        int br = idx >= N_EDGES;
        int e  = idx - br * N_EDGES;
        int d  = br ? dst2[e] : dst1[e];
        int s  = br ? src2[e] : src1[e];
        int p  = atomicAdd(&cursorAll[br * N_NODES + d], 1);
        csrAll[br * N_EDGES + p] = s;
    }
}

// ---------------------------------------------------------------------------
// Warp-per-node gather of fp16-packed features: one uint4 per lane per row.
// fp32 accumulation, fp16-packed output.
// ---------------------------------------------------------------------------
__global__ __launch_bounds__(256)
void gather_f16(const uint32_t* __restrict__ nfQ,
                const int* __restrict__ rowstart,
                const int* __restrict__ csr,
                uint32_t* __restrict__ aggQ)
{
    int node = (blockIdx.x * blockDim.x + threadIdx.x) >> 5;
    int lane = threadIdx.x & 31;
    if (node >= N_NODES) return;

    int beg = rowstart[node], end = rowstart[node + 1];
    float a[8];
    #pragma unroll
    for (int i = 0; i < 8; i++) a[i] = 0.f;
    float b[8];
    #pragma unroll
    for (int i = 0; i < 8; i++) b[i] = 0.f;

    int e = beg;
    for (; e + 1 < end; e += 2) {
        uint4 u = reinterpret_cast<const uint4*>(nfQ + (size_t)csr[e]     * 128)[lane];
        uint4 v = reinterpret_cast<const uint4*>(nfQ + (size_t)csr[e + 1] * 128)[lane];
        float2 f;
        f = unpack_f16(u.x); a[0] += f.x; a[1] += f.y;
        f = unpack_f16(u.y); a[2] += f.x; a[3] += f.y;
        f = unpack_f16(u.z); a[4] += f.x; a[5] += f.y;
        f = unpack_f16(u.w); a[6] += f.x; a[7] += f.y;
        f = unpack_f16(v.x); b[0] += f.x; b[1] += f.y;
        f = unpack_f16(v.y); b[2] += f.x; b[3] += f.y;
        f = unpack_f16(v.z); b[4] += f.x; b[5] += f.y;
        f = unpack_f16(v.w); b[6] += f.x; b[7] += f.y;
    }
    if (e < end) {
        uint4 u = reinterpret_cast<const uint4*>(nfQ + (size_t)csr[e] * 128)[lane];
        float2 f;
        f = unpack_f16(u.x); a[0] += f.x; a[1] += f.y;
        f = unpack_f16(u.y); a[2] += f.x; a[3] += f.y;
        f = unpack_f16(u.z); a[4] += f.x; a[5] += f.y;
        f = unpack_f16(u.w); a[6] += f.x; a[7] += f.y;
    }
    #pragma unroll
    for (int i = 0; i < 8; i++) a[i] += b[i];

    uint4 o;
    o.x = pack_f16(a[0], a[1]);
    o.y = pack_f16(a[2], a[3]);
    o.z = pack_f16(a[4], a[5]);
    o.w = pack_f16(a[6], a[7]);
    reinterpret_cast<uint4*>(aggQ + (size_t)node * 128)[lane] = o;
}

// ---------------------------------------------------------------------------
// Segment sum over fp16-packed h2 (sorted gid); 128 threads = 128 word-cols.
// ---------------------------------------------------------------------------
__global__ __launch_bounds__(128)
void segsum_kernel(const uint32_t* __restrict__ h2Q, const int* __restrict__ gid,
                   float* __restrict__ T, int* __restrict__ counts)
{
    __shared__ int sb, se;
    int g = blockIdx.x;
    if (threadIdx.x == 0) {
        int lo = 0, hi = N_NODES;
        while (lo < hi) { int m = (lo + hi) >> 1; if (gid[m] < g) lo = m + 1; else hi = m; }
        sb = lo;
        lo = sb; hi = N_NODES;
        while (lo < hi) { int m = (lo + hi) >> 1; if (gid[m] < g + 1) lo = m + 1; else hi = m; }
        se = lo;
        counts[g] = se - sb;
    }
    __syncthreads();
    int beg = sb, end = se, wc = threadIdx.x;
    float sx = 0.f, sy = 0.f;
    for (int r = beg; r < end; r++) {
        float2 f = unpack_f16(h2Q[(size_t)r * 128 + wc]);
        sx += f.x; sy += f.y;
    }
    *reinterpret_cast<float2*>(T + (size_t)g * DFEAT + 2 * wc) = make_float2(sx, sy);
}

// ---------------------------------------------------------------------------
// Fused readout + predictor
// ---------------------------------------------------------------------------
__global__ __launch_bounds__(256)
void readout_final(const float* __restrict__ TAll, const int* __restrict__ countsAll,
                   const float* __restrict__ Ro1, const float* __restrict__ rbo1,
                   const float* __restrict__ Ro2, const float* __restrict__ rbo2,
                   const float* __restrict__ Wp, const float* __restrict__ bp,
                   float* __restrict__ out)
{
    __shared__ float ts1[DFEAT], ts2[DFEAT];
    __shared__ float red[256];
    int g = blockIdx.x;
    int t = threadIdx.x;
    ts1[t] = TAll[(size_t)g * DFEAT + t];
    ts2[t] = TAll[((size_t)N_GRAPHS + g) * DFEAT + t];
    __syncthreads();
    float c1 = (float)countsAll[g];
    float c2 = (float)countsAll[N_GRAPHS + g];
    float partial = 0.f;
    if (t < G_FEAT) {
        float s = c1 * rbo1[t] + c2 * rbo2[t];
        #pragma unroll 8
        for (int k = 0; k < DFEAT; k++)
            s += ts1[k] * Ro1[(size_t)k * G_FEAT + t]
               + ts2[k] * Ro2[(size_t)k * G_FEAT + t];
        partial = s * Wp[t];
    }
    red[t] = partial;
    __syncthreads();
    #pragma unroll
    for (int st = 128; st > 0; st >>= 1) {
        if (t < st) red[t] += red[t + st];
        __syncthreads();
    }
    if (t == 0) out[g] = red[0] + bp[0];
}

// ---------------------------------------------------------------------------
extern "C" void kernel_launch(void* const* d_in, const int* in_sizes, int n_in,
                              void* d_out, int out_size)
{
    const float* nf1 = (const float*)d_in[0];
    const float* nf2 = (const float*)d_in[2];
    const int* src1 = (const int*)d_in[4];
    const int* dst1 = (const int*)d_in[5];
    const int* gid1 = (const int*)d_in[6];
    const int* src2 = (const int*)d_in[7];
    const int* dst2 = (const int*)d_in[8];
    const int* gid2 = (const int*)d_in[9];
    const float* W1  = (const float*)d_in[10]; const float* b1  = (const float*)d_in[11];
    const float* Wr1 = (const float*)d_in[12]; const float* br1 = (const float*)d_in[13];
    const float* W2  = (const float*)d_in[14]; const float* b2  = (const float*)d_in[15];
    const float* Wr2 = (const float*)d_in[16]; const float* br2 = (const float*)d_in[17];
    const float* Ri1 = (const float*)d_in[18]; const float* rbi1 = (const float*)d_in[19];
    const float* Ro1 = (const float*)d_in[20]; const float* rbo1 = (const float*)d_in[21];
    const float* Ri2 = (const float*)d_in[22]; const float* rbi2 = (const float*)d_in[23];
    const float* Ro2 = (const float*)d_in[24]; const float* rbo2 = (const float*)d_in[25];
    const float* Wp  = (const float*)d_in[26]; const float* bp   = (const float*)d_in[27];

    float *T;
    uint32_t *t2Q, *aggQ, *nfQ, *h1Q, *WQ;
    int *counts, *deg, *rowstart, *cursor, *csr_src, *bsums;
    cudaGetSymbolAddress((void**)&t2Q,      g_t2Q);
    cudaGetSymbolAddress((void**)&aggQ,     g_aggQ);
    cudaGetSymbolAddress((void**)&nfQ,      g_nfQ);
    cudaGetSymbolAddress((void**)&h1Q,      g_h1Q);
    cudaGetSymbolAddress((void**)&WQ,       g_WQ);
    cudaGetSymbolAddress((void**)&T,        g_T);
    cudaGetSymbolAddress((void**)&counts,   g_counts);
    cudaGetSymbolAddress((void**)&deg,      g_deg);
    cudaGetSymbolAddress((void**)&rowstart, g_rowstart);
    cudaGetSymbolAddress((void**)&cursor,   g_cursor);
    cudaGetSymbolAddress((void**)&csr_src,  g_csr_src);
    cudaGetSymbolAddress((void**)&bsums,    g_bsums);

    cudaFuncSetAttribute(gemm_mma<0>, cudaFuncAttributeMaxDynamicSharedMemorySize, SMEM_BYTES);
    cudaFuncSetAttribute(gemm_mma<1>, cudaFuncAttributeMaxDynamicSharedMemorySize, SMEM_BYTES);
    cudaFuncSetAttribute(gemm_mma<2>, cudaFuncAttributeMaxDynamicSharedMemorySize, SMEM_BYTES);

    static cudaStream_t s_s2 = nullptr, s_s3 = nullptr;
    static cudaEvent_t  s_evF = nullptr, s_evNF = nullptr, s_evConv = nullptr,
                        s_evG1 = nullptr, s_evG2 = nullptr, s_evJ3 = nullptr;
    static bool s_tried = false;
    if (!s_tried) {
        s_tried = true;
        bool ok =
            cudaStreamCreateWithFlags(&s_s2, cudaStreamNonBlocking) == cudaSuccess &&
            cudaStreamCreateWithFlags(&s_s3, cudaStreamNonBlocking) == cudaSuccess &&
            cudaEventCreateWithFlags(&s_evF,    cudaEventDisableTiming) == cudaSuccess &&
            cudaEventCreateWithFlags(&s_evNF,   cudaEventDisableTiming) == cudaSuccess &&
            cudaEventCreateWithFlags(&s_evConv, cudaEventDisableTiming) == cudaSuccess &&
            cudaEventCreateWithFlags(&s_evG1,   cudaEventDisableTiming) == cudaSuccess &&
            cudaEventCreateWithFlags(&s_evG2,   cudaEventDisableTiming) == cudaSuccess &&
            cudaEventCreateWithFlags(&s_evJ3,   cudaEventDisableTiming) == cudaSuccess;
        if (!ok) { s_s2 = nullptr; s_s3 = nullptr; }
    }
    const bool par = (s_s2 != nullptr);
    cudaStream_t s0 = (cudaStream_t)0;
    cudaStream_t s2 = par ? s_s2 : s0;
    cudaStream_t s3 = par ? s_s3 : s0;

    uint32_t* t2Q1 = t2Q;   uint32_t* t2Q2 = t2Q + (size_t)NW;
    float* T1   = T;    float* T2   = T  + (size_t)N_GRAPHS * DFEAT;
    int* counts1 = counts;  int* counts2 = counts + N_GRAPHS;
    uint32_t* aggQ1 = aggQ; uint32_t* aggQ2 = aggQ + (size_t)NW;
    uint32_t* nfQ1 = nfQ;   uint32_t* nfQ2 = nfQ + (size_t)NW;
    uint32_t* h1Q1 = h1Q;   uint32_t* h1Q2 = h1Q + (size_t)NW;
    const int* rs1 = rowstart;              const int* rs2 = rowstart + (N_NODES + 1);
    const int* cs1 = csr_src;               const int* cs2 = csr_src + N_EDGES;
    const int WSZ = 128 * 256;   // slots: 0=W1 1=Wr1 2=Ri1 3=W2 4=Wr2 5=Ri2

    dim3 gemm_grid((N_NODES + 127) / 128, 2);       // per-branch: 391 x 2
    int eb2 = (2 * N_EDGES + 255) / 256;
    int gat_blocks = (N_NODES * 32 + 255) / 256;

    // ---- fork ----
    if (par) {
        cudaEventRecord(s_evF, s0);
        cudaStreamWaitEvent(s_s2, s_evF, 0);
        cudaStreamWaitEvent(s_s3, s_evF, 0);
    }

    // s0: conversions first (gathers depend on conv_nf)
    conv_nf<<<(int)((2 * (size_t)NW + 255) / 256), 256, 0, s0>>>(nf1, nf2, nfQ);
    if (par) cudaEventRecord(s_evNF, s0);
    conv_W<<<(6 * 128 * 256 + 255) / 256, 256, 0, s0>>>(W1, Wr1, Ri1, W2, Wr2, Ri2, WQ);
    if (par) cudaEventRecord(s_evConv, s0);

    // s2: CSR chain, then both fp16 gathers (wait conv_nf)
    cudaMemsetAsync(deg, 0, 2 * N_NODES * sizeof(int), s2);
    hist_kernel<<<eb2, 256, 0, s2>>>(dst1, dst2, deg);
    scan1_kernel<<<2 * SCAN_BLKS, 256, 0, s2>>>(deg, rowstart, bsums);
    scan2_kernel<<<2 * SCAN_BLKS, 256, 0, s2>>>(bsums, rowstart, cursor);
    fill_kernel<<<eb2, 256, 0, s2>>>(src1, dst1, src2, dst2, cursor, csr_src);
    if (par) cudaStreamWaitEvent(s_s2, s_evNF, 0);
    gather_f16<<<gat_blocks, 256, 0, s2>>>(nfQ1, rs1, cs1, aggQ1);
    if (par) cudaEventRecord(s_evG1, s_s2);
    gather_f16<<<gat_blocks, 256, 0, s2>>>(nfQ2, rs2, cs2, aggQ2);
    if (par) cudaEventRecord(s_evG2, s_s2);

    // s0: branch-1 GEMM chain
    gemm_mma<0><<<gemm_grid, 256, SMEM_BYTES, s0>>>(
        nfQ1, WQ + 1 * WSZ, nullptr, nullptr, nullptr, t2Q1, N_NODES);
    if (par) cudaStreamWaitEvent(s0, s_evG1, 0);
    gemm_mma<1><<<gemm_grid, 256, SMEM_BYTES, s0>>>(
        aggQ1, WQ + 0 * WSZ, b1, t2Q1, br1, h1Q1, N_NODES);
    gemm_mma<2><<<gemm_grid, 256, SMEM_BYTES, s0>>>(
        h1Q1, WQ + 2 * WSZ, rbi1, nullptr, nullptr, t2Q1, N_NODES);
    segsum_kernel<<<N_GRAPHS, 128, 0, s0>>>(t2Q1, gid1, T1, counts1);

    // s3: branch-2 GEMM chain
    if (par) cudaStreamWaitEvent(s_s3, s_evConv, 0);
    gemm_mma<0><<<gemm_grid, 256, SMEM_BYTES, s3>>>(
        nfQ2, WQ + 4 * WSZ, nullptr, nullptr, nullptr, t2Q2, N_NODES);
    if (par) cudaStreamWaitEvent(s_s3, s_evG2, 0);
    gemm_mma<1><<<gemm_grid, 256, SMEM_BYTES, s3>>>(
        aggQ2, WQ + 3 * WSZ, b2, t2Q2, br2, h1Q2, N_NODES);
    gemm_mma<2><<<gemm_grid, 256, SMEM_BYTES, s3>>>(
        h1Q2, WQ + 5 * WSZ, rbi2, nullptr, nullptr, t2Q2, N_NODES);
    segsum_kernel<<<N_GRAPHS, 128, 0, s3>>>(t2Q2, gid2, T2, counts2);
    if (par) cudaEventRecord(s_evJ3, s_s3);

    // join + fused readout/predictor
    if (par) cudaStreamWaitEvent(s0, s_evJ3, 0);
    readout_final<<<N_GRAPHS, 256, 0, s0>>>(T, counts, Ro1, rbo1, Ro2, rbo2, Wp, bp,
                                            (float*)d_out);
}